// round 7
// baseline (speedup 1.0000x reference)
#include <cuda_runtime.h>
#include <cuda_bf16.h>

#define BB 4
#define SS 1024
#define DD 1024
#define HH 16
#define DHH 64
#define EE 8
#define FFF 2048
#define NTOK (BB*SS)
#define D3 (3*DD)
#define EFF (EE*FFF)

// ---------------------------------------------------------------------------
// Scratch (static device globals — allocations are forbidden).
// ---------------------------------------------------------------------------
__device__ float g_attn[(size_t)NTOK*DD];
__device__ float g_x[(size_t)NTOK*DD];
__device__ float g_ff[(size_t)NTOK*DD];
__device__ float g_gates[(size_t)NTOK*EE];

__device__ __nv_bfloat16 g_srcH[(size_t)NTOK*DD],  g_srcL[(size_t)NTOK*DD];
__device__ __nv_bfloat16 g_wqH[(size_t)D3*DD],     g_wqL[(size_t)D3*DD];
__device__ __nv_bfloat16 g_woH[(size_t)DD*DD],     g_woL[(size_t)DD*DD];
__device__ __nv_bfloat16 g_w1H[(size_t)EFF*DD],    g_w1L[(size_t)EFF*DD];
__device__ __nv_bfloat16 g_w2H[(size_t)DD*EFF],    g_w2L[(size_t)DD*EFF];
__device__ __nv_bfloat16 g_qkvH[(size_t)NTOK*D3],  g_qkvL[(size_t)NTOK*D3];
__device__ __nv_bfloat16 g_vtH[(size_t)BB*HH*DHH*SS], g_vtL[(size_t)BB*HH*DHH*SS];
__device__ __nv_bfloat16 g_ctxH[(size_t)NTOK*DD],  g_ctxL[(size_t)NTOK*DD];
__device__ __nv_bfloat16 g_xH[(size_t)NTOK*DD],    g_xL[(size_t)NTOK*DD];
__device__ __nv_bfloat16 g_hH[(size_t)NTOK*EFF],   g_hL[(size_t)NTOK*EFF];

// ---------------------------------------------------------------------------
// PTX helpers (sm_80-era instructions only — legal on plain sm_103 target).
// ---------------------------------------------------------------------------
__device__ __forceinline__ unsigned smem_u32(const void* p){
    unsigned a;
    asm("{ .reg .u64 t; cvta.to.shared.u64 t, %1; cvt.u32.u64 %0, t; }" : "=r"(a) : "l"(p));
    return a;
}
__device__ __forceinline__ void cp16(unsigned saddr, const void* gaddr){
    asm volatile("cp.async.cg.shared.global [%0], [%1], 16;" :: "r"(saddr), "l"(gaddr));
}
#define CP_COMMIT() asm volatile("cp.async.commit_group;" ::: "memory")
template<int N> __device__ __forceinline__ void cp_wait(){
    asm volatile("cp.async.wait_group %0;" :: "n"(N) : "memory");
}
__device__ __forceinline__ void ldsm_x4(unsigned addr, unsigned* r){
    asm volatile("ldmatrix.sync.aligned.m8n8.x4.shared.b16 {%0,%1,%2,%3}, [%4];"
        : "=r"(r[0]),"=r"(r[1]),"=r"(r[2]),"=r"(r[3]) : "r"(addr));
}
__device__ __forceinline__ void mma16816(float* c, const unsigned* a, const unsigned* b){
    asm volatile("mma.sync.aligned.m16n8k16.row.col.f32.bf16.bf16.f32 "
        "{%0,%1,%2,%3}, {%4,%5,%6,%7}, {%8,%9}, {%0,%1,%2,%3};"
        : "+f"(c[0]),"+f"(c[1]),"+f"(c[2]),"+f"(c[3])
        : "r"(a[0]),"r"(a[1]),"r"(a[2]),"r"(a[3]), "r"(b[0]),"r"(b[1]));
}
__device__ __forceinline__ unsigned packbf2(float lo, float hi){
    __nv_bfloat162 t = __floats2bfloat162_rn(lo, hi);   // .x = lo (low half)
    return *reinterpret_cast<unsigned*>(&t);
}

// ---------------------------------------------------------------------------
// bf16x3 split GEMM via mma.sync.  C[M,N] = epi( alpha * (A @ B^T) )
//   BM=128, BN=256, BK=32. Warp tile 64x64 (MF=4, NF=8), 8 warps, 1 CTA/SM.
//   Dedup per ks: load aH,bH,bL -> aH*bH, aH*bL -> load aL (reuse regs) -> aL*bH.
// ---------------------------------------------------------------------------
template<int BN, bool RELU, bool GATE, bool OUTPAIR>
__global__ void __launch_bounds__(256, 1) mma_gemm(
    const __nv_bfloat16* __restrict__ Ahi, const __nv_bfloat16* __restrict__ Alo,
    const __nv_bfloat16* __restrict__ Bhi, const __nv_bfloat16* __restrict__ Blo,
    float* __restrict__ C, __nv_bfloat16* __restrict__ Chi, __nv_bfloat16* __restrict__ Clo,
    int K, int lda, int ldb, int ldc, int Hbatch,
    long long aSB, long long aSH, long long bSB, long long bSH,
    long long cSB, long long cSH,
    const float* __restrict__ bias, const float* __restrict__ gates, float alpha)
{
    constexpr int WX = 4;                 // warps along N
    constexpr int WY = 2;                 // warps along M
    constexpr int WN = BN / WX;           // 64
    constexpr int WM = 128 / WY;          // 64
    constexpr int MF = WM / 16;           // 4
    constexpr int NF = WN / 8;            // 8
    constexpr unsigned APITCH = 80u;
    constexpr unsigned ABYTES = 128u * APITCH;        // 10240
    constexpr unsigned BNB    = (unsigned)BN * APITCH;
    constexpr unsigned STAGE  = 2u * ABYTES + 2u * BNB;

    extern __shared__ char smem[];
    const unsigned sb = smem_u32(smem);
    const int tid = threadIdx.x, w = tid >> 5, lane = tid & 31;
    const int wy = w / WX, wx = w % WX;
    const int wm0 = wy * WM, wn0 = wx * WN;

    const int z  = blockIdx.z;
    const int zb = z / Hbatch, zh = z % Hbatch;
    Ahi += zb * aSB + zh * aSH;  Alo += zb * aSB + zh * aSH;
    Bhi += zb * bSB + zh * bSH;  Blo += zb * bSB + zh * bSH;
    if (OUTPAIR) { Chi += zb * cSB + zh * cSH; Clo += zb * cSB + zh * cSH; }
    else         { C   += zb * cSB + zh * cSH; }

    const int row0 = blockIdx.y * 128;
    const int col0 = blockIdx.x * BN;
    const int NC = K >> 5;

    auto loadChunk = [&](int c, int s){
        const unsigned st = sb + (unsigned)s * STAGE;
        for (int i = tid; i < 512; i += 256) {
            int r = i >> 2, ch = i & 3;
            unsigned so = st + (unsigned)r * APITCH + (unsigned)ch * 16u;
            const char* gH = (const char*)(Ahi + (long long)(row0 + r) * lda + c * 32) + ch * 16;
            const char* gL = (const char*)(Alo + (long long)(row0 + r) * lda + c * 32) + ch * 16;
            cp16(so, gH);
            cp16(so + ABYTES, gL);
        }
        for (int i = tid; i < BN * 4; i += 256) {
            int r = i >> 2, ch = i & 3;
            unsigned so = st + 2u * ABYTES + (unsigned)r * APITCH + (unsigned)ch * 16u;
            const char* gH = (const char*)(Bhi + (long long)(col0 + r) * ldb + c * 32) + ch * 16;
            const char* gL = (const char*)(Blo + (long long)(col0 + r) * ldb + c * 32) + ch * 16;
            cp16(so, gH);
            cp16(so + BNB, gL);
        }
        CP_COMMIT();
    };

    float cr[MF][NF][4];
#pragma unroll
    for (int i = 0; i < MF; i++)
#pragma unroll
        for (int j = 0; j < NF; j++)
#pragma unroll
            for (int q = 0; q < 4; q++) cr[i][j][q] = 0.f;

    loadChunk(0, 0);

    for (int c = 0; c < NC; c++) {
        if (c + 1 < NC) { loadChunk(c + 1, (c + 1) & 1); cp_wait<1>(); }
        else            { cp_wait<0>(); }
        __syncthreads();

        const unsigned st  = sb + (unsigned)(c & 1) * STAGE;
        const unsigned aHB = st;
        const unsigned aLB = st + ABYTES;
        const unsigned bHB = st + 2u * ABYTES;
        const unsigned bLB = st + 2u * ABYTES + BNB;

#pragma unroll
        for (int ks = 0; ks < 2; ks++) {
            const unsigned aRow = (unsigned)(wm0 + (lane & 15)) * APITCH
                                + (unsigned)(ks * 2 + (lane >> 4)) * 16u;
            const unsigned bRow = (unsigned)(wn0 + (lane & 7) + ((lane >> 4) << 3)) * APITCH
                                + (unsigned)(ks * 2 + ((lane >> 3) & 1)) * 16u;

            unsigned aF[MF][4];
#pragma unroll
            for (int mf = 0; mf < MF; mf++)
                ldsm_x4(aHB + aRow + (unsigned)(mf * 16) * APITCH, aF[mf]);

            unsigned bH[NF][2], bL[NF][2];
#pragma unroll
            for (int nfp = 0; nfp < NF/2; nfp++) {
                unsigned off = bRow + (unsigned)(nfp * 16) * APITCH;
                unsigned t[4];
                ldsm_x4(bHB + off, t);
                bH[nfp*2][0] = t[0]; bH[nfp*2][1] = t[1];
                bH[nfp*2+1][0] = t[2]; bH[nfp*2+1][1] = t[3];
                ldsm_x4(bLB + off, t);
                bL[nfp*2][0] = t[0]; bL[nfp*2][1] = t[1];
                bL[nfp*2+1][0] = t[2]; bL[nfp*2+1][1] = t[3];
            }

#pragma unroll
            for (int mf = 0; mf < MF; mf++)
#pragma unroll
                for (int nf = 0; nf < NF; nf++)
                    mma16816(cr[mf][nf], aF[mf], bH[nf]);
#pragma unroll
            for (int mf = 0; mf < MF; mf++)
#pragma unroll
                for (int nf = 0; nf < NF; nf++)
                    mma16816(cr[mf][nf], aF[mf], bL[nf]);

#pragma unroll
            for (int mf = 0; mf < MF; mf++)
                ldsm_x4(aLB + aRow + (unsigned)(mf * 16) * APITCH, aF[mf]);
#pragma unroll
            for (int mf = 0; mf < MF; mf++)
#pragma unroll
                for (int nf = 0; nf < NF; nf++)
                    mma16816(cr[mf][nf], aF[mf], bH[nf]);
        }
        __syncthreads();
    }

    // ---- epilogue: vectorized pair stores (n, n+1 adjacent) ----
    auto epi2 = [&](int m, int n, float v0, float v1){
        v0 *= alpha; v1 *= alpha;
        if (bias) { v0 += bias[n]; v1 += bias[n + 1]; }
        if (RELU) { v0 = fmaxf(v0, 0.f); v1 = fmaxf(v1, 0.f); }
        if (GATE) {
            float gt = gates[(long long)m * EE + (n / FFF)];
            v0 *= gt; v1 *= gt;
        }
        if (OUTPAIR) {
            __nv_bfloat162 hh = __floats2bfloat162_rn(v0, v1);
            __nv_bfloat162 ll = __floats2bfloat162_rn(v0 - __bfloat162float(hh.x),
                                                      v1 - __bfloat162float(hh.y));
            *reinterpret_cast<__nv_bfloat162*>(Chi + (long long)m * ldc + n) = hh;
            *reinterpret_cast<__nv_bfloat162*>(Clo + (long long)m * ldc + n) = ll;
        } else {
            float2 f = make_float2(v0, v1);
            *reinterpret_cast<float2*>(C + (long long)m * ldc + n) = f;
        }
    };
#pragma unroll
    for (int mf = 0; mf < MF; mf++) {
        const int m = row0 + wm0 + mf * 16 + (lane >> 2);
#pragma unroll
        for (int nf = 0; nf < NF; nf++) {
            const int n = col0 + wn0 + nf * 8 + (lane & 3) * 2;
            epi2(m,     n, cr[mf][nf][0], cr[mf][nf][1]);
            epi2(m + 8, n, cr[mf][nf][2], cr[mf][nf][3]);
        }
    }
}

// ---------------------------------------------------------------------------
// Flash attention: one CTA = (b,h) x 128-query tile. 8 warps, each 16 rows.
// ---------------------------------------------------------------------------
__global__ void __launch_bounds__(256) flash_kernel(
    const __nv_bfloat16* __restrict__ qkvH, const __nv_bfloat16* __restrict__ qkvL,
    const __nv_bfloat16* __restrict__ vtH,  const __nv_bfloat16* __restrict__ vtL,
    __nv_bfloat16* __restrict__ cH, __nv_bfloat16* __restrict__ cL)
{
    constexpr unsigned QP = 144u, VP = 272u;
    constexpr unsigned QBYTES = 128u * QP;
    constexpr unsigned KBYTES = 128u * QP;
    constexpr unsigned VBYTES = 64u * VP;
    constexpr unsigned STAGE  = 2u * KBYTES + 2u * VBYTES;

    extern __shared__ char smem[];
    const unsigned sb = smem_u32(smem);
    const int tid = threadIdx.x, w = tid >> 5, lane = tid & 31;

    const int bh = blockIdx.z, b = bh >> 4, h = bh & 15;
    const int q0 = blockIdx.x * 128;

    const __nv_bfloat16* Qh = qkvH + ((long long)b * SS) * D3 + h * DHH;
    const __nv_bfloat16* Ql = qkvL + ((long long)b * SS) * D3 + h * DHH;
    const __nv_bfloat16* Kh = Qh + DD;
    const __nv_bfloat16* Kl = Ql + DD;
    const __nv_bfloat16* Vh = vtH + (long long)bh * DHH * SS;
    const __nv_bfloat16* Vl = vtL + (long long)bh * DHH * SS;

    const unsigned qHB = sb, qLB = sb + QBYTES;
    const unsigned kvBase = sb + 2u * QBYTES;

    for (int i = tid; i < 1024; i += 256) {
        int r = i >> 3, ch = i & 7;
        unsigned so = (unsigned)r * QP + (unsigned)ch * 16u;
        const char* gH = (const char*)(Qh + (long long)(q0 + r) * D3) + ch * 16;
        const char* gL = (const char*)(Ql + (long long)(q0 + r) * D3) + ch * 16;
        cp16(qHB + so, gH);
        cp16(qLB + so, gL);
    }

    auto loadKV = [&](int t, int s){
        const unsigned st = kvBase + (unsigned)s * STAGE;
        const int k0 = t * 128;
        for (int i = tid; i < 1024; i += 256) {
            int r = i >> 3, ch = i & 7;
            unsigned so = st + (unsigned)r * QP + (unsigned)ch * 16u;
            const char* gH = (const char*)(Kh + (long long)(k0 + r) * D3) + ch * 16;
            const char* gL = (const char*)(Kl + (long long)(k0 + r) * D3) + ch * 16;
            cp16(so, gH);
            cp16(so + KBYTES, gL);
        }
        const unsigned vst = st + 2u * KBYTES;
        for (int i = tid; i < 1024; i += 256) {
            int r = i >> 4, ch = i & 15;
            unsigned so = vst + (unsigned)r * VP + (unsigned)ch * 16u;
            const char* gH = (const char*)(Vh + (long long)r * SS + k0) + ch * 16;
            const char* gL = (const char*)(Vl + (long long)r * SS + k0) + ch * 16;
            cp16(so, gH);
            cp16(so + VBYTES, gL);
        }
        CP_COMMIT();
    };
    loadKV(0, 0);

    float o[8][4];
#pragma unroll
    for (int i = 0; i < 8; i++)
#pragma unroll
        for (int q = 0; q < 4; q++) o[i][q] = 0.f;
    float m0 = -1e30f, m1 = -1e30f, l0 = 0.f, l1 = 0.f;
    const float scale = 0.125f;

    for (int t = 0; t < 8; t++) {
        if (t + 1 < 8) { loadKV(t + 1, (t + 1) & 1); cp_wait<1>(); }
        else           { cp_wait<0>(); }
        __syncthreads();

        const unsigned st  = kvBase + (unsigned)(t & 1) * STAGE;
        const unsigned kHB = st, kLB = st + KBYTES;
        const unsigned vHB = st + 2u * KBYTES, vLB = vHB + VBYTES;

        float sc[16][4];
#pragma unroll
        for (int i = 0; i < 16; i++)
#pragma unroll
            for (int q = 0; q < 4; q++) sc[i][q] = 0.f;

#pragma unroll
        for (int ks = 0; ks < 4; ks++) {
            const unsigned aRow = (unsigned)(w * 16 + (lane & 15)) * QP
                                + (unsigned)(ks * 2 + (lane >> 4)) * 16u;
            unsigned aH[4], aL[4];
            ldsm_x4(qHB + aRow, aH);
            ldsm_x4(qLB + aRow, aL);
#pragma unroll
            for (int nfp = 0; nfp < 8; nfp++) {
                const unsigned bo = (unsigned)(nfp * 16 + (lane & 7) + ((lane >> 4) << 3)) * QP
                                  + (unsigned)(ks * 2 + ((lane >> 3) & 1)) * 16u;
                unsigned tH[4], tL[4];
                ldsm_x4(kHB + bo, tH);
                ldsm_x4(kLB + bo, tL);
                mma16816(sc[nfp*2],   aH, tH);
                mma16816(sc[nfp*2+1], aH, tH + 2);
                mma16816(sc[nfp*2],   aL, tH);
                mma16816(sc[nfp*2+1], aL, tH + 2);
                mma16816(sc[nfp*2],   aH, tL);
                mma16816(sc[nfp*2+1], aH, tL + 2);
            }
        }

        float r0 = -1e30f, r1 = -1e30f;
#pragma unroll
        for (int i = 0; i < 16; i++) {
            r0 = fmaxf(r0, fmaxf(sc[i][0], sc[i][1]));
            r1 = fmaxf(r1, fmaxf(sc[i][2], sc[i][3]));
        }
        r0 = fmaxf(r0, __shfl_xor_sync(0xffffffff, r0, 1));
        r0 = fmaxf(r0, __shfl_xor_sync(0xffffffff, r0, 2));
        r1 = fmaxf(r1, __shfl_xor_sync(0xffffffff, r1, 1));
        r1 = fmaxf(r1, __shfl_xor_sync(0xffffffff, r1, 2));
        const float mn0 = fmaxf(m0, r0 * scale);
        const float mn1 = fmaxf(m1, r1 * scale);
        const float cor0 = __expf(m0 - mn0);
        const float cor1 = __expf(m1 - mn1);
        m0 = mn0; m1 = mn1;

        float s0 = 0.f, s1 = 0.f;
#pragma unroll
        for (int i = 0; i < 16; i++) {
            sc[i][0] = __expf(sc[i][0] * scale - m0);
            sc[i][1] = __expf(sc[i][1] * scale - m0);
            sc[i][2] = __expf(sc[i][2] * scale - m1);
            sc[i][3] = __expf(sc[i][3] * scale - m1);
            s0 += sc[i][0] + sc[i][1];
            s1 += sc[i][2] + sc[i][3];
        }
        s0 += __shfl_xor_sync(0xffffffff, s0, 1);
        s0 += __shfl_xor_sync(0xffffffff, s0, 2);
        s1 += __shfl_xor_sync(0xffffffff, s1, 1);
        s1 += __shfl_xor_sync(0xffffffff, s1, 2);
        l0 = l0 * cor0 + s0;
        l1 = l1 * cor1 + s1;
#pragma unroll
        for (int i = 0; i < 8; i++) {
            o[i][0] *= cor0; o[i][1] *= cor0;
            o[i][2] *= cor1; o[i][3] *= cor1;
        }

#pragma unroll
        for (int kv = 0; kv < 8; kv++) {
            float* p0 = sc[kv*2];
            float* p1 = sc[kv*2+1];
            unsigned aH[4], aL[4];
            {
                __nv_bfloat16 h00 = __float2bfloat16(p0[0]), h01 = __float2bfloat16(p0[1]);
                __nv_bfloat16 h02 = __float2bfloat16(p0[2]), h03 = __float2bfloat16(p0[3]);
                __nv_bfloat16 h10 = __float2bfloat16(p1[0]), h11 = __float2bfloat16(p1[1]);
                __nv_bfloat16 h12 = __float2bfloat16(p1[2]), h13 = __float2bfloat16(p1[3]);
                aH[0] = ((unsigned)__bfloat16_as_ushort(h01) << 16) | __bfloat16_as_ushort(h00);
                aH[1] = ((unsigned)__bfloat16_as_ushort(h03) << 16) | __bfloat16_as_ushort(h02);
                aH[2] = ((unsigned)__bfloat16_as_ushort(h11) << 16) | __bfloat16_as_ushort(h10);
                aH[3] = ((unsigned)__bfloat16_as_ushort(h13) << 16) | __bfloat16_as_ushort(h12);
                aL[0] = packbf2(p0[0] - __bfloat162float(h00), p0[1] - __bfloat162float(h01));
                aL[1] = packbf2(p0[2] - __bfloat162float(h02), p0[3] - __bfloat162float(h03));
                aL[2] = packbf2(p1[0] - __bfloat162float(h10), p1[1] - __bfloat162float(h11));
                aL[3] = packbf2(p1[2] - __bfloat162float(h12), p1[3] - __bfloat162float(h13));
            }
#pragma unroll
            for (int vf = 0; vf < 4; vf++) {
                const unsigned bo = (unsigned)(vf * 16 + (lane & 7) + ((lane >> 4) << 3)) * VP
                                  + (unsigned)(kv * 2 + ((lane >> 3) & 1)) * 16u;
                unsigned tH[4], tL[4];
                ldsm_x4(vHB + bo, tH);
                ldsm_x4(vLB + bo, tL);
                mma16816(o[vf*2],   aH, tH);
                mma16816(o[vf*2+1], aH, tH + 2);
                mma16816(o[vf*2],   aL, tH);
                mma16816(o[vf*2+1], aL, tH + 2);
                mma16816(o[vf*2],   aH, tL);
                mma16816(o[vf*2+1], aH, tL + 2);
            }
        }
        __syncthreads();
    }

    const float inv0 = 1.f / l0, inv1 = 1.f / l1;
    const int r = q0 + w * 16 + (lane >> 2);
    const long long tok0 = (long long)(b * SS + r);
    const long long tok1 = tok0 + 8;
#pragma unroll
    for (int nf = 0; nf < 8; nf++) {
        const int d = h * DHH + nf * 8 + (lane & 3) * 2;
#pragma unroll
        for (int q = 0; q < 2; q++) {
            float v0 = o[nf][q]     * inv0;
            float v1 = o[nf][2 + q] * inv1;
            __nv_bfloat16 h0 = __float2bfloat16(v0);
            __nv_bfloat16 h1 = __float2bfloat16(v1);
            cH[tok0 * DD + d + q] = h0;
            cL[tok0 * DD + d + q] = __float2bfloat16(v0 - __bfloat162float(h0));
            cH[tok1 * DD + d + q] = h1;
            cL[tok1 * DD + d + q] = __float2bfloat16(v1 - __bfloat162float(h1));
        }
    }
}

// ---------------------------------------------------------------------------
// fp32 -> bf16 hi/lo split (elementwise)
// ---------------------------------------------------------------------------
__global__ void split_kernel(const float* __restrict__ in,
                             __nv_bfloat16* __restrict__ oh, __nv_bfloat16* __restrict__ ol,
                             long long n)
{
    long long i = (long long)blockIdx.x * blockDim.x + threadIdx.x;
    long long stride = (long long)gridDim.x * blockDim.x;
    for (; i < n; i += stride) {
        float v = in[i];
        __nv_bfloat16 h = __float2bfloat16(v);
        oh[i] = h;
        ol[i] = __float2bfloat16(v - __bfloat162float(h));
    }
}

// ---------------------------------------------------------------------------
// Transpose + split: fp32 [R][C] (ldin) -> pair [C][R] (ldout), per z.
// ---------------------------------------------------------------------------
__global__ void tsplit_kernel(const float* __restrict__ in,
                              __nv_bfloat16* __restrict__ oh, __nv_bfloat16* __restrict__ ol,
                              int ldin, int ldout, long long inStride, long long outStride)
{
    __shared__ float t[32][33];
    in += (long long)blockIdx.z * inStride;
    oh += (long long)blockIdx.z * outStride;
    ol += (long long)blockIdx.z * outStride;
    const int c0 = blockIdx.x * 32, r0 = blockIdx.y * 32;
    const int tx = threadIdx.x & 31, ty = threadIdx.x >> 5;
#pragma unroll
    for (int j = 0; j < 4; j++)
        t[ty + j * 8][tx] = in[(long long)(r0 + ty + j * 8) * ldin + c0 + tx];
    __syncthreads();
#pragma unroll
    for (int j = 0; j < 4; j++) {
        float v = t[tx][ty + j * 8];
        __nv_bfloat16 h = __float2bfloat16(v);
        long long o = (long long)(c0 + ty + j * 8) * ldout + r0 + tx;
        oh[o] = h;
        ol[o] = __float2bfloat16(v - __bfloat162float(h));
    }
}

// ---------------------------------------------------------------------------
// V transpose: qkv pair -> vt pair [z][DHH][SS].
// ---------------------------------------------------------------------------
__global__ void vtrans_kernel(const __nv_bfloat16* __restrict__ qH,
                              const __nv_bfloat16* __restrict__ qL,
                              __nv_bfloat16* __restrict__ vH, __nv_bfloat16* __restrict__ vL)
{
    __shared__ __nv_bfloat16 tH[32][33], tL[32][33];
    const int zc = blockIdx.z, zbb = zc / HH, zhh = zc % HH;
    const __nv_bfloat16* bH = qH + (long long)(zbb * SS) * D3 + 2 * DD + zhh * DHH;
    const __nv_bfloat16* bL = qL + (long long)(zbb * SS) * D3 + 2 * DD + zhh * DHH;
    const int t0 = blockIdx.x * 32, d0 = blockIdx.y * 32;
    const int tx = threadIdx.x & 31, ty = threadIdx.x >> 5;
#pragma unroll
    for (int j = 0; j < 4; j++) {
        long long src = (long long)(t0 + ty + j * 8) * D3 + d0 + tx;
        tH[ty + j * 8][tx] = bH[src];
        tL[ty + j * 8][tx] = bL[src];
    }
    __syncthreads();
    __nv_bfloat16* oH = vH + (long long)zc * DHH * SS;
    __nv_bfloat16* oL = vL + (long long)zc * DHH * SS;
#pragma unroll
    for (int j = 0; j < 4; j++) {
        long long dst = (long long)(d0 + ty + j * 8) * SS + t0 + tx;
        oH[dst] = tH[tx][ty + j * 8];
        oL[dst] = tL[tx][ty + j * 8];
    }
}

// ---------------------------------------------------------------------------
// out = LN(a + b [+ gates@b2]) * g + beta ; optional bf16 pair output.
// ---------------------------------------------------------------------------
__global__ void ln_kernel(const float* __restrict__ a, const float* __restrict__ b,
                          const float* __restrict__ g, const float* __restrict__ beta,
                          float* __restrict__ outF,
                          __nv_bfloat16* __restrict__ oh, __nv_bfloat16* __restrict__ ol,
                          const float* __restrict__ gates, const float* __restrict__ b2)
{
    long long row = blockIdx.x;
    const float* ar = a + row * DD;
    const float* br = b + row * DD;
    __shared__ float red[256];
    int tid = threadIdx.x;

    float gt[EE];
    if (gates) {
#pragma unroll
        for (int e = 0; e < EE; e++) gt[e] = gates[row * EE + e];
    }

    float v[4]; float s = 0.f;
#pragma unroll
    for (int i = 0; i < 4; i++) {
        int c = tid + i * 256;
        float x = ar[c] + br[c];
        if (gates) {
            float s2 = 0.f;
#pragma unroll
            for (int e = 0; e < EE; e++) s2 += gt[e] * b2[e * DD + c];
            x += s2;
        }
        v[i] = x; s += x;
    }
    red[tid] = s; __syncthreads();
    for (int t = 128; t; t >>= 1) { if (tid < t) red[tid] += red[tid + t]; __syncthreads(); }
    float mean = red[0] * (1.f / DD); __syncthreads();

    float sq = 0.f;
#pragma unroll
    for (int i = 0; i < 4; i++) { float d = v[i] - mean; sq += d * d; }
    red[tid] = sq; __syncthreads();
    for (int t = 128; t; t >>= 1) { if (tid < t) red[tid] += red[tid + t]; __syncthreads(); }
    float inv = rsqrtf(red[0] * (1.f / DD) + 1e-5f);

#pragma unroll
    for (int i = 0; i < 4; i++) {
        int c = tid + i * 256;
        float o = (v[i] - mean) * inv * g[c] + beta[c];
        outF[row * DD + c] = o;
        if (oh) {
            __nv_bfloat16 h = __float2bfloat16(o);
            oh[row * DD + c] = h;
            ol[row * DD + c] = __float2bfloat16(o - __bfloat162float(h));
        }
    }
}

// ---------------------------------------------------------------------------
// Gate: softmax(x @ gate_w^T + gate_b) over E=8. One warp per token.
// ---------------------------------------------------------------------------
__global__ void gate_kernel(const float* __restrict__ x, const float* __restrict__ gw,
                            const float* __restrict__ gb, float* __restrict__ gates)
{
    int warp = (blockIdx.x * blockDim.x + threadIdx.x) >> 5;
    int lane = threadIdx.x & 31;
    if (warp >= NTOK) return;
    const float* xr = x + (long long)warp * DD;

    float p[EE];
#pragma unroll
    for (int e = 0; e < EE; e++) p[e] = 0.f;
    for (int d = lane; d < DD; d += 32) {
        float xv = xr[d];
#pragma unroll
        for (int e = 0; e < EE; e++) p[e] += xv * gw[e * DD + d];
    }
#pragma unroll
    for (int e = 0; e < EE; e++)
        for (int off = 16; off; off >>= 1)
            p[e] += __shfl_xor_sync(0xffffffff, p[e], off);

    if (lane == 0) {
        float mx = -3.4e38f;
#pragma unroll
        for (int e = 0; e < EE; e++) { p[e] += gb[e]; mx = fmaxf(mx, p[e]); }
        float sm = 0.f;
#pragma unroll
        for (int e = 0; e < EE; e++) { p[e] = expf(p[e] - mx); sm += p[e]; }
        float inv = 1.f / sm;
#pragma unroll
        for (int e = 0; e < EE; e++) gates[(long long)warp * EE + e] = p[e] * inv;
    }
}

// ---------------------------------------------------------------------------
// Host orchestration (graph-capturable: launches only).
// ---------------------------------------------------------------------------
extern "C" void kernel_launch(void* const* d_in, const int* in_sizes, int n_in,
                              void* d_out, int out_size)
{
    const float* src        = (const float*)d_in[0];
    const float* in_proj_w  = (const float*)d_in[2];
    const float* in_proj_b  = (const float*)d_in[3];
    const float* out_proj_w = (const float*)d_in[4];
    const float* out_proj_b = (const float*)d_in[5];
    const float* gate_w     = (const float*)d_in[6];
    const float* gate_b     = (const float*)d_in[7];
    const float* w1         = (const float*)d_in[8];
    const float* b1         = (const float*)d_in[9];
    const float* w2         = (const float*)d_in[10];
    const float* b2         = (const float*)d_in[11];
    const float* ln1_g      = (const float*)d_in[12];
    const float* ln1_b      = (const float*)d_in[13];
    const float* ln2_g      = (const float*)d_in[14];
    const float* ln2_b      = (const float*)d_in[15];
    float* out = (float*)d_out;

    float *attn, *x, *ff, *gates;
    cudaGetSymbolAddress((void**)&attn,   g_attn);
    cudaGetSymbolAddress((void**)&x,      g_x);
    cudaGetSymbolAddress((void**)&ff,     g_ff);
    cudaGetSymbolAddress((void**)&gates,  g_gates);

    __nv_bfloat16 *srcH,*srcL,*wqH,*wqL,*woH,*woL,*w1H,*w1L,*w2H,*w2L;
    __nv_bfloat16 *qkvH,*qkvL,*vtH,*vtL,*ctxH,*ctxL,*xH,*xL,*hH,*hL;
    cudaGetSymbolAddress((void**)&srcH, g_srcH); cudaGetSymbolAddress((void**)&srcL, g_srcL);
    cudaGetSymbolAddress((void**)&wqH,  g_wqH);  cudaGetSymbolAddress((void**)&wqL,  g_wqL);
    cudaGetSymbolAddress((void**)&woH,  g_woH);  cudaGetSymbolAddress((void**)&woL,  g_woL);
    cudaGetSymbolAddress((void**)&w1H,  g_w1H);  cudaGetSymbolAddress((void**)&w1L,  g_w1L);
    cudaGetSymbolAddress((void**)&w2H,  g_w2H);  cudaGetSymbolAddress((void**)&w2L,  g_w2L);
    cudaGetSymbolAddress((void**)&qkvH, g_qkvH); cudaGetSymbolAddress((void**)&qkvL, g_qkvL);
    cudaGetSymbolAddress((void**)&vtH,  g_vtH);  cudaGetSymbolAddress((void**)&vtL,  g_vtL);
    cudaGetSymbolAddress((void**)&ctxH, g_ctxH); cudaGetSymbolAddress((void**)&ctxL, g_ctxL);
    cudaGetSymbolAddress((void**)&xH,   g_xH);   cudaGetSymbolAddress((void**)&xL,   g_xL);
    cudaGetSymbolAddress((void**)&hH,   g_hH);   cudaGetSymbolAddress((void**)&hL,   g_hL);

    const int SM256 = 2 * (2 * 10240 + 2 * 256 * 80);           // 122880
    const int SMFA  = 2 * 18432 + 2 * (2 * 18432 + 2 * 17408);  // 180224
    cudaFuncSetAttribute(mma_gemm<256,false,false,true >, cudaFuncAttributeMaxDynamicSharedMemorySize, SM256);
    cudaFuncSetAttribute(mma_gemm<256,false,false,false>, cudaFuncAttributeMaxDynamicSharedMemorySize, SM256);
    cudaFuncSetAttribute(mma_gemm<256,true ,true ,true >, cudaFuncAttributeMaxDynamicSharedMemorySize, SM256);
    cudaFuncSetAttribute(flash_kernel, cudaFuncAttributeMaxDynamicSharedMemorySize, SMFA);

    dim3 blk(256);

    // ---- conversions ----
    split_kernel<<<2048, 256>>>(src,        srcH, srcL, (long long)NTOK * DD);
    split_kernel<<<2048, 256>>>(in_proj_w,  wqH,  wqL,  (long long)D3 * DD);
    split_kernel<<<1024, 256>>>(out_proj_w, woH,  woL,  (long long)DD * DD);
    tsplit_kernel<<<dim3(FFF/32, DD/32, EE), blk>>>(w1, w1H, w1L, FFF, DD,
        (long long)DD * FFF, (long long)FFF * DD);
    tsplit_kernel<<<dim3(DD/32, FFF/32, EE), blk>>>(w2, w2H, w2L, DD, EFF,
        (long long)FFF * DD, (long long)FFF);

    // ---- 1. qkv pair = src @ in_proj_w^T + b ----
    mma_gemm<256,false,false,true><<<dim3(D3/256, NTOK/128, 1), blk, SM256>>>(
        srcH, srcL, wqH, wqL, nullptr, qkvH, qkvL,
        DD, DD, DD, D3, 1, 0,0, 0,0, 0,0, in_proj_b, nullptr, 1.f);

    // ---- 2. v transpose ----
    vtrans_kernel<<<dim3(SS/32, DHH/32, BB*HH), blk>>>(qkvH, qkvL, vtH, vtL);

    // ---- 3. flash attention -> ctx pair ----
    flash_kernel<<<dim3(SS/128, 1, BB*HH), blk, SMFA>>>(
        qkvH, qkvL, vtH, vtL, ctxH, ctxL);

    // ---- 4. attn = ctx @ out_proj_w^T + b (fp32) ----
    mma_gemm<256,false,false,false><<<dim3(DD/256, NTOK/128, 1), blk, SM256>>>(
        ctxH, ctxL, woH, woL, attn, nullptr, nullptr,
        DD, DD, DD, DD, 1, 0,0, 0,0, 0,0, out_proj_b, nullptr, 1.f);

    // ---- 5. x = LN1(src + attn), fp32 + pair ----
    ln_kernel<<<NTOK, blk>>>(src, attn, ln1_g, ln1_b, x, xH, xL, nullptr, nullptr);

    // ---- 6. gates ----
    gate_kernel<<<NTOK/8, blk>>>(x, gate_w, gate_b, gates);

    // ---- 7. h' pair = gate * relu(x @ w1t^T + b1)   [4096, 16384] ----
    mma_gemm<256,true,true,true><<<dim3(EFF/256, NTOK/128, 1), blk, SM256>>>(
        xH, xL, w1H, w1L, nullptr, hH, hL,
        DD, DD, DD, EFF, 1, 0,0, 0,0, 0,0, b1, gates, 1.f);

    // ---- 8. ff = h' @ w2t^T (fp32), K=16384 ----
    mma_gemm<256,false,false,false><<<dim3(DD/256, NTOK/128, 1), blk, SM256>>>(
        hH, hL, w2H, w2L, ff, nullptr, nullptr,
        EFF, EFF, EFF, DD, 1, 0,0, 0,0, 0,0, nullptr, nullptr, 1.f);

    // ---- 9. out = LN2(x + ff + gates@b2) ----
    ln_kernel<<<NTOK, blk>>>(x, ff, ln2_g, ln2_b, out, nullptr, nullptr, gates, b2);
}

// round 8
// speedup vs baseline: 1.1189x; 1.1189x over previous
#include <cuda_runtime.h>
#include <cuda_bf16.h>

#define BB 4
#define SS 1024
#define DD 1024
#define HH 16
#define DHH 64
#define EE 8
#define FFF 2048
#define NTOK (BB*SS)
#define D3 (3*DD)
#define EFF (EE*FFF)

// ---------------------------------------------------------------------------
// Scratch (static device globals — allocations are forbidden).
// ---------------------------------------------------------------------------
__device__ float g_attn[(size_t)NTOK*DD];
__device__ float g_x[(size_t)NTOK*DD];
__device__ float g_ff[(size_t)NTOK*DD];
__device__ float g_gates[(size_t)NTOK*EE];

__device__ __nv_bfloat16 g_srcH[(size_t)NTOK*DD],  g_srcL[(size_t)NTOK*DD];
__device__ __nv_bfloat16 g_wqH[(size_t)D3*DD],     g_wqL[(size_t)D3*DD];
__device__ __nv_bfloat16 g_woH[(size_t)DD*DD],     g_woL[(size_t)DD*DD];
__device__ __nv_bfloat16 g_w1H[(size_t)EFF*DD],    g_w1L[(size_t)EFF*DD];
__device__ __nv_bfloat16 g_w2H[(size_t)DD*EFF],    g_w2L[(size_t)DD*EFF];
__device__ __nv_bfloat16 g_qkvH[(size_t)NTOK*D3],  g_qkvL[(size_t)NTOK*D3];
__device__ __nv_bfloat16 g_vtH[(size_t)BB*HH*DHH*SS], g_vtL[(size_t)BB*HH*DHH*SS];
__device__ __nv_bfloat16 g_ctxH[(size_t)NTOK*DD],  g_ctxL[(size_t)NTOK*DD];
__device__ __nv_bfloat16 g_xH[(size_t)NTOK*DD],    g_xL[(size_t)NTOK*DD];
__device__ __nv_bfloat16 g_hH[(size_t)NTOK*EFF],   g_hL[(size_t)NTOK*EFF];

// ---------------------------------------------------------------------------
// PTX helpers (sm_80-era instructions only — legal on plain sm_103 target).
// ---------------------------------------------------------------------------
__device__ __forceinline__ unsigned smem_u32(const void* p){
    unsigned a;
    asm("{ .reg .u64 t; cvta.to.shared.u64 t, %1; cvt.u32.u64 %0, t; }" : "=r"(a) : "l"(p));
    return a;
}
__device__ __forceinline__ void cp16(unsigned saddr, const void* gaddr){
    asm volatile("cp.async.cg.shared.global [%0], [%1], 16;" :: "r"(saddr), "l"(gaddr));
}
#define CP_COMMIT() asm volatile("cp.async.commit_group;" ::: "memory")
template<int N> __device__ __forceinline__ void cp_wait(){
    asm volatile("cp.async.wait_group %0;" :: "n"(N) : "memory");
}
__device__ __forceinline__ void ldsm_x4(unsigned addr, unsigned* r){
    asm volatile("ldmatrix.sync.aligned.m8n8.x4.shared.b16 {%0,%1,%2,%3}, [%4];"
        : "=r"(r[0]),"=r"(r[1]),"=r"(r[2]),"=r"(r[3]) : "r"(addr));
}
__device__ __forceinline__ void mma16816(float* c, const unsigned* a, const unsigned* b){
    asm volatile("mma.sync.aligned.m16n8k16.row.col.f32.bf16.bf16.f32 "
        "{%0,%1,%2,%3}, {%4,%5,%6,%7}, {%8,%9}, {%0,%1,%2,%3};"
        : "+f"(c[0]),"+f"(c[1]),"+f"(c[2]),"+f"(c[3])
        : "r"(a[0]),"r"(a[1]),"r"(a[2]),"r"(a[3]), "r"(b[0]),"r"(b[1]));
}
__device__ __forceinline__ unsigned packbf2(float lo, float hi){
    __nv_bfloat162 t = __floats2bfloat162_rn(lo, hi);   // .x = lo (low half)
    return *reinterpret_cast<unsigned*>(&t);
}

// ---------------------------------------------------------------------------
// bf16x3 split GEMM via mma.sync.  C[M,N] = epi( alpha * (A @ B^T) )
//   BM=128, BN=128, BK=32, warp tile 64x32 (MF=4, NF=4), 2 CTAs/SM.
//   Fragment dedup: aH,bH,bL -> aH*bH + aH*bL -> aL (reuse regs) -> aL*bH.
//   Epilogue staged through smem for fully coalesced 16B global stores.
// ---------------------------------------------------------------------------
template<int BN, bool RELU, bool GATE, bool OUTPAIR>
__global__ void __launch_bounds__(256, 2) mma_gemm(
    const __nv_bfloat16* __restrict__ Ahi, const __nv_bfloat16* __restrict__ Alo,
    const __nv_bfloat16* __restrict__ Bhi, const __nv_bfloat16* __restrict__ Blo,
    float* __restrict__ C, __nv_bfloat16* __restrict__ Chi, __nv_bfloat16* __restrict__ Clo,
    int K, int lda, int ldb, int ldc, int Hbatch,
    long long aSB, long long aSH, long long bSB, long long bSH,
    long long cSB, long long cSH,
    const float* __restrict__ bias, const float* __restrict__ gates, float alpha)
{
    constexpr int WX = BN / 32;          // warps along N (4)
    constexpr int WY = 8 / WX;           // warps along M (2)
    constexpr int WM = 128 / WY;         // 64
    constexpr int MF = WM / 16;          // 4
    constexpr int NF = 4;                // warp N tile = 32
    constexpr unsigned APITCH = 80u;
    constexpr unsigned ABYTES = 128u * APITCH;        // 10240
    constexpr unsigned BNB    = (unsigned)BN * APITCH;
    constexpr unsigned STAGE  = 2u * ABYTES + 2u * BNB;

    extern __shared__ char smem[];
    const unsigned sb = smem_u32(smem);
    const int tid = threadIdx.x, w = tid >> 5, lane = tid & 31;
    const int wy = w / WX, wx = w % WX;
    const int wm0 = wy * WM, wn0 = wx * 32;

    const int z  = blockIdx.z;
    const int zb = z / Hbatch, zh = z % Hbatch;
    Ahi += zb * aSB + zh * aSH;  Alo += zb * aSB + zh * aSH;
    Bhi += zb * bSB + zh * bSH;  Blo += zb * bSB + zh * bSH;
    if (OUTPAIR) { Chi += zb * cSB + zh * cSH; Clo += zb * cSB + zh * cSH; }
    else         { C   += zb * cSB + zh * cSH; }

    const int row0 = blockIdx.y * 128;
    const int col0 = blockIdx.x * BN;
    const int NC = K >> 5;

    auto loadChunk = [&](int c, int s){
        const unsigned st = sb + (unsigned)s * STAGE;
        for (int i = tid; i < 512; i += 256) {
            int r = i >> 2, ch = i & 3;
            unsigned so = st + (unsigned)r * APITCH + (unsigned)ch * 16u;
            const char* gH = (const char*)(Ahi + (long long)(row0 + r) * lda + c * 32) + ch * 16;
            const char* gL = (const char*)(Alo + (long long)(row0 + r) * lda + c * 32) + ch * 16;
            cp16(so, gH);
            cp16(so + ABYTES, gL);
        }
        for (int i = tid; i < BN * 4; i += 256) {
            int r = i >> 2, ch = i & 3;
            unsigned so = st + 2u * ABYTES + (unsigned)r * APITCH + (unsigned)ch * 16u;
            const char* gH = (const char*)(Bhi + (long long)(col0 + r) * ldb + c * 32) + ch * 16;
            const char* gL = (const char*)(Blo + (long long)(col0 + r) * ldb + c * 32) + ch * 16;
            cp16(so, gH);
            cp16(so + BNB, gL);
        }
        CP_COMMIT();
    };

    float cr[MF][NF][4];
#pragma unroll
    for (int i = 0; i < MF; i++)
#pragma unroll
        for (int j = 0; j < NF; j++)
#pragma unroll
            for (int q = 0; q < 4; q++) cr[i][j][q] = 0.f;

    loadChunk(0, 0);

    for (int c = 0; c < NC; c++) {
        if (c + 1 < NC) { loadChunk(c + 1, (c + 1) & 1); cp_wait<1>(); }
        else            { cp_wait<0>(); }
        __syncthreads();

        const unsigned st  = sb + (unsigned)(c & 1) * STAGE;
        const unsigned aHB = st;
        const unsigned aLB = st + ABYTES;
        const unsigned bHB = st + 2u * ABYTES;
        const unsigned bLB = st + 2u * ABYTES + BNB;

#pragma unroll
        for (int ks = 0; ks < 2; ks++) {
            const unsigned aRow = (unsigned)(wm0 + (lane & 15)) * APITCH
                                + (unsigned)(ks * 2 + (lane >> 4)) * 16u;
            const unsigned bRow = (unsigned)(wn0 + (lane & 7) + ((lane >> 4) << 3)) * APITCH
                                + (unsigned)(ks * 2 + ((lane >> 3) & 1)) * 16u;

            unsigned aF[MF][4];
#pragma unroll
            for (int mf = 0; mf < MF; mf++)
                ldsm_x4(aHB + aRow + (unsigned)(mf * 16) * APITCH, aF[mf]);

            unsigned bH[NF][2], bL[NF][2];
#pragma unroll
            for (int nfp = 0; nfp < NF/2; nfp++) {
                unsigned off = bRow + (unsigned)(nfp * 16) * APITCH;
                unsigned t[4];
                ldsm_x4(bHB + off, t);
                bH[nfp*2][0] = t[0]; bH[nfp*2][1] = t[1];
                bH[nfp*2+1][0] = t[2]; bH[nfp*2+1][1] = t[3];
                ldsm_x4(bLB + off, t);
                bL[nfp*2][0] = t[0]; bL[nfp*2][1] = t[1];
                bL[nfp*2+1][0] = t[2]; bL[nfp*2+1][1] = t[3];
            }

#pragma unroll
            for (int mf = 0; mf < MF; mf++)
#pragma unroll
                for (int nf = 0; nf < NF; nf++)
                    mma16816(cr[mf][nf], aF[mf], bH[nf]);
#pragma unroll
            for (int mf = 0; mf < MF; mf++)
#pragma unroll
                for (int nf = 0; nf < NF; nf++)
                    mma16816(cr[mf][nf], aF[mf], bL[nf]);

#pragma unroll
            for (int mf = 0; mf < MF; mf++)
                ldsm_x4(aLB + aRow + (unsigned)(mf * 16) * APITCH, aF[mf]);
#pragma unroll
            for (int mf = 0; mf < MF; mf++)
#pragma unroll
                for (int nf = 0; nf < NF; nf++)
                    mma16816(cr[mf][nf], aF[mf], bH[nf]);
        }
        __syncthreads();
    }

    // ---- epilogue: apply math per fragment, stage in smem, coalesced copy ----
    // Pitches padded by 16B -> rows shift 4 banks; frag stores conflict-free.
    constexpr unsigned PP = (unsigned)BN * 2u + 16u;   // bf16 tile row pitch
    constexpr unsigned PF = (unsigned)BN * 4u + 16u;   // fp32 tile row pitch

    auto emath = [&](int m, int n, float& v0, float& v1){
        v0 *= alpha; v1 *= alpha;
        if (bias) { v0 += bias[n]; v1 += bias[n + 1]; }
        if (RELU) { v0 = fmaxf(v0, 0.f); v1 = fmaxf(v1, 0.f); }
        if (GATE) {
            float gt = gates[(long long)m * EE + (n / FFF)];
            v0 *= gt; v1 *= gt;
        }
    };

#pragma unroll
    for (int mf = 0; mf < MF; mf++) {
        const int ml = wm0 + mf * 16 + (lane >> 2);
#pragma unroll
        for (int nf = 0; nf < NF; nf++) {
            const int nl = wn0 + nf * 8 + (lane & 3) * 2;
            const int n  = col0 + nl;
            float a0 = cr[mf][nf][0], a1 = cr[mf][nf][1];
            float b0 = cr[mf][nf][2], b1 = cr[mf][nf][3];
            emath(row0 + ml,     n, a0, a1);
            emath(row0 + ml + 8, n, b0, b1);
            if (OUTPAIR) {
                __nv_bfloat162 hh0 = __floats2bfloat162_rn(a0, a1);
                __nv_bfloat162 ll0 = __floats2bfloat162_rn(a0 - __bfloat162float(hh0.x),
                                                           a1 - __bfloat162float(hh0.y));
                __nv_bfloat162 hh1 = __floats2bfloat162_rn(b0, b1);
                __nv_bfloat162 ll1 = __floats2bfloat162_rn(b0 - __bfloat162float(hh1.x),
                                                           b1 - __bfloat162float(hh1.y));
                *reinterpret_cast<__nv_bfloat162*>(smem + (unsigned)ml * PP + (unsigned)nl * 2u) = hh0;
                *reinterpret_cast<__nv_bfloat162*>(smem + 128u*PP + (unsigned)ml * PP + (unsigned)nl * 2u) = ll0;
                *reinterpret_cast<__nv_bfloat162*>(smem + (unsigned)(ml+8) * PP + (unsigned)nl * 2u) = hh1;
                *reinterpret_cast<__nv_bfloat162*>(smem + 128u*PP + (unsigned)(ml+8) * PP + (unsigned)nl * 2u) = ll1;
            } else {
                *reinterpret_cast<float2*>(smem + (unsigned)ml * PF + (unsigned)nl * 4u) = make_float2(a0, a1);
                *reinterpret_cast<float2*>(smem + (unsigned)(ml+8) * PF + (unsigned)nl * 4u) = make_float2(b0, b1);
            }
        }
    }
    __syncthreads();

    if (OUTPAIR) {
        constexpr int CH = BN / 8;                    // 16B chunks per row
        for (int i = tid; i < 128 * CH; i += 256) {
            int r = i / CH, ch = i % CH;
            uint4 hv = *reinterpret_cast<uint4*>(smem + (unsigned)r * PP + (unsigned)ch * 16u);
            uint4 lv = *reinterpret_cast<uint4*>(smem + 128u*PP + (unsigned)r * PP + (unsigned)ch * 16u);
            long long base = (long long)(row0 + r) * ldc + col0 + ch * 8;
            *reinterpret_cast<uint4*>(Chi + base) = hv;
            *reinterpret_cast<uint4*>(Clo + base) = lv;
        }
    } else {
        constexpr int CHF = BN / 4;                   // 16B chunks per row
        for (int i = tid; i < 128 * CHF; i += 256) {
            int r = i / CHF, ch = i % CHF;
            uint4 v = *reinterpret_cast<uint4*>(smem + (unsigned)r * PF + (unsigned)ch * 16u);
            long long base = (long long)(row0 + r) * ldc + col0 + ch * 4;
            *reinterpret_cast<uint4*>(C + base) = v;
        }
    }
}

// ---------------------------------------------------------------------------
// Flash attention: one CTA = (b,h) x 128-query tile. 8 warps, each 16 rows.
// ---------------------------------------------------------------------------
__global__ void __launch_bounds__(256) flash_kernel(
    const __nv_bfloat16* __restrict__ qkvH, const __nv_bfloat16* __restrict__ qkvL,
    const __nv_bfloat16* __restrict__ vtH,  const __nv_bfloat16* __restrict__ vtL,
    __nv_bfloat16* __restrict__ cH, __nv_bfloat16* __restrict__ cL)
{
    constexpr unsigned QP = 144u, VP = 272u;
    constexpr unsigned QBYTES = 128u * QP;
    constexpr unsigned KBYTES = 128u * QP;
    constexpr unsigned VBYTES = 64u * VP;
    constexpr unsigned STAGE  = 2u * KBYTES + 2u * VBYTES;

    extern __shared__ char smem[];
    const unsigned sb = smem_u32(smem);
    const int tid = threadIdx.x, w = tid >> 5, lane = tid & 31;

    const int bh = blockIdx.z, b = bh >> 4, h = bh & 15;
    const int q0 = blockIdx.x * 128;

    const __nv_bfloat16* Qh = qkvH + ((long long)b * SS) * D3 + h * DHH;
    const __nv_bfloat16* Ql = qkvL + ((long long)b * SS) * D3 + h * DHH;
    const __nv_bfloat16* Kh = Qh + DD;
    const __nv_bfloat16* Kl = Ql + DD;
    const __nv_bfloat16* Vh = vtH + (long long)bh * DHH * SS;
    const __nv_bfloat16* Vl = vtL + (long long)bh * DHH * SS;

    const unsigned qHB = sb, qLB = sb + QBYTES;
    const unsigned kvBase = sb + 2u * QBYTES;

    for (int i = tid; i < 1024; i += 256) {
        int r = i >> 3, ch = i & 7;
        unsigned so = (unsigned)r * QP + (unsigned)ch * 16u;
        const char* gH = (const char*)(Qh + (long long)(q0 + r) * D3) + ch * 16;
        const char* gL = (const char*)(Ql + (long long)(q0 + r) * D3) + ch * 16;
        cp16(qHB + so, gH);
        cp16(qLB + so, gL);
    }

    auto loadKV = [&](int t, int s){
        const unsigned st = kvBase + (unsigned)s * STAGE;
        const int k0 = t * 128;
        for (int i = tid; i < 1024; i += 256) {
            int r = i >> 3, ch = i & 7;
            unsigned so = st + (unsigned)r * QP + (unsigned)ch * 16u;
            const char* gH = (const char*)(Kh + (long long)(k0 + r) * D3) + ch * 16;
            const char* gL = (const char*)(Kl + (long long)(k0 + r) * D3) + ch * 16;
            cp16(so, gH);
            cp16(so + KBYTES, gL);
        }
        const unsigned vst = st + 2u * KBYTES;
        for (int i = tid; i < 1024; i += 256) {
            int r = i >> 4, ch = i & 15;
            unsigned so = vst + (unsigned)r * VP + (unsigned)ch * 16u;
            const char* gH = (const char*)(Vh + (long long)r * SS + k0) + ch * 16;
            const char* gL = (const char*)(Vl + (long long)r * SS + k0) + ch * 16;
            cp16(so, gH);
            cp16(so + VBYTES, gL);
        }
        CP_COMMIT();
    };
    loadKV(0, 0);

    float o[8][4];
#pragma unroll
    for (int i = 0; i < 8; i++)
#pragma unroll
        for (int q = 0; q < 4; q++) o[i][q] = 0.f;
    float m0 = -1e30f, m1 = -1e30f, l0 = 0.f, l1 = 0.f;
    const float scale = 0.125f;

    for (int t = 0; t < 8; t++) {
        if (t + 1 < 8) { loadKV(t + 1, (t + 1) & 1); cp_wait<1>(); }
        else           { cp_wait<0>(); }
        __syncthreads();

        const unsigned st  = kvBase + (unsigned)(t & 1) * STAGE;
        const unsigned kHB = st, kLB = st + KBYTES;
        const unsigned vHB = st + 2u * KBYTES, vLB = vHB + VBYTES;

        float sc[16][4];
#pragma unroll
        for (int i = 0; i < 16; i++)
#pragma unroll
            for (int q = 0; q < 4; q++) sc[i][q] = 0.f;

#pragma unroll
        for (int ks = 0; ks < 4; ks++) {
            const unsigned aRow = (unsigned)(w * 16 + (lane & 15)) * QP
                                + (unsigned)(ks * 2 + (lane >> 4)) * 16u;
            unsigned aH[4], aL[4];
            ldsm_x4(qHB + aRow, aH);
            ldsm_x4(qLB + aRow, aL);
#pragma unroll
            for (int nfp = 0; nfp < 8; nfp++) {
                const unsigned bo = (unsigned)(nfp * 16 + (lane & 7) + ((lane >> 4) << 3)) * QP
                                  + (unsigned)(ks * 2 + ((lane >> 3) & 1)) * 16u;
                unsigned tH[4], tL[4];
                ldsm_x4(kHB + bo, tH);
                ldsm_x4(kLB + bo, tL);
                mma16816(sc[nfp*2],   aH, tH);
                mma16816(sc[nfp*2+1], aH, tH + 2);
                mma16816(sc[nfp*2],   aL, tH);
                mma16816(sc[nfp*2+1], aL, tH + 2);
                mma16816(sc[nfp*2],   aH, tL);
                mma16816(sc[nfp*2+1], aH, tL + 2);
            }
        }

        float r0 = -1e30f, r1 = -1e30f;
#pragma unroll
        for (int i = 0; i < 16; i++) {
            r0 = fmaxf(r0, fmaxf(sc[i][0], sc[i][1]));
            r1 = fmaxf(r1, fmaxf(sc[i][2], sc[i][3]));
        }
        r0 = fmaxf(r0, __shfl_xor_sync(0xffffffff, r0, 1));
        r0 = fmaxf(r0, __shfl_xor_sync(0xffffffff, r0, 2));
        r1 = fmaxf(r1, __shfl_xor_sync(0xffffffff, r1, 1));
        r1 = fmaxf(r1, __shfl_xor_sync(0xffffffff, r1, 2));
        const float mn0 = fmaxf(m0, r0 * scale);
        const float mn1 = fmaxf(m1, r1 * scale);
        const float cor0 = __expf(m0 - mn0);
        const float cor1 = __expf(m1 - mn1);
        m0 = mn0; m1 = mn1;

        float s0 = 0.f, s1 = 0.f;
#pragma unroll
        for (int i = 0; i < 16; i++) {
            sc[i][0] = __expf(sc[i][0] * scale - m0);
            sc[i][1] = __expf(sc[i][1] * scale - m0);
            sc[i][2] = __expf(sc[i][2] * scale - m1);
            sc[i][3] = __expf(sc[i][3] * scale - m1);
            s0 += sc[i][0] + sc[i][1];
            s1 += sc[i][2] + sc[i][3];
        }
        s0 += __shfl_xor_sync(0xffffffff, s0, 1);
        s0 += __shfl_xor_sync(0xffffffff, s0, 2);
        s1 += __shfl_xor_sync(0xffffffff, s1, 1);
        s1 += __shfl_xor_sync(0xffffffff, s1, 2);
        l0 = l0 * cor0 + s0;
        l1 = l1 * cor1 + s1;
#pragma unroll
        for (int i = 0; i < 8; i++) {
            o[i][0] *= cor0; o[i][1] *= cor0;
            o[i][2] *= cor1; o[i][3] *= cor1;
        }

#pragma unroll
        for (int kv = 0; kv < 8; kv++) {
            float* p0 = sc[kv*2];
            float* p1 = sc[kv*2+1];
            unsigned aH[4], aL[4];
            {
                __nv_bfloat16 h00 = __float2bfloat16(p0[0]), h01 = __float2bfloat16(p0[1]);
                __nv_bfloat16 h02 = __float2bfloat16(p0[2]), h03 = __float2bfloat16(p0[3]);
                __nv_bfloat16 h10 = __float2bfloat16(p1[0]), h11 = __float2bfloat16(p1[1]);
                __nv_bfloat16 h12 = __float2bfloat16(p1[2]), h13 = __float2bfloat16(p1[3]);
                aH[0] = ((unsigned)__bfloat16_as_ushort(h01) << 16) | __bfloat16_as_ushort(h00);
                aH[1] = ((unsigned)__bfloat16_as_ushort(h03) << 16) | __bfloat16_as_ushort(h02);
                aH[2] = ((unsigned)__bfloat16_as_ushort(h11) << 16) | __bfloat16_as_ushort(h10);
                aH[3] = ((unsigned)__bfloat16_as_ushort(h13) << 16) | __bfloat16_as_ushort(h12);
                aL[0] = packbf2(p0[0] - __bfloat162float(h00), p0[1] - __bfloat162float(h01));
                aL[1] = packbf2(p0[2] - __bfloat162float(h02), p0[3] - __bfloat162float(h03));
                aL[2] = packbf2(p1[0] - __bfloat162float(h10), p1[1] - __bfloat162float(h11));
                aL[3] = packbf2(p1[2] - __bfloat162float(h12), p1[3] - __bfloat162float(h13));
            }
#pragma unroll
            for (int vf = 0; vf < 4; vf++) {
                const unsigned bo = (unsigned)(vf * 16 + (lane & 7) + ((lane >> 4) << 3)) * VP
                                  + (unsigned)(kv * 2 + ((lane >> 3) & 1)) * 16u;
                unsigned tH[4], tL[4];
                ldsm_x4(vHB + bo, tH);
                ldsm_x4(vLB + bo, tL);
                mma16816(o[vf*2],   aH, tH);
                mma16816(o[vf*2+1], aH, tH + 2);
                mma16816(o[vf*2],   aL, tH);
                mma16816(o[vf*2+1], aL, tH + 2);
                mma16816(o[vf*2],   aH, tL);
                mma16816(o[vf*2+1], aH, tL + 2);
            }
        }
        __syncthreads();
    }

    const float inv0 = 1.f / l0, inv1 = 1.f / l1;
    const int r = q0 + w * 16 + (lane >> 2);
    const long long tok0 = (long long)(b * SS + r);
    const long long tok1 = tok0 + 8;
#pragma unroll
    for (int nf = 0; nf < 8; nf++) {
        const int d = h * DHH + nf * 8 + (lane & 3) * 2;
#pragma unroll
        for (int q = 0; q < 2; q++) {
            float v0 = o[nf][q]     * inv0;
            float v1 = o[nf][2 + q] * inv1;
            __nv_bfloat16 h0 = __float2bfloat16(v0);
            __nv_bfloat16 h1 = __float2bfloat16(v1);
            cH[tok0 * DD + d + q] = h0;
            cL[tok0 * DD + d + q] = __float2bfloat16(v0 - __bfloat162float(h0));
            cH[tok1 * DD + d + q] = h1;
            cL[tok1 * DD + d + q] = __float2bfloat16(v1 - __bfloat162float(h1));
        }
    }
}

// ---------------------------------------------------------------------------
// fp32 -> bf16 hi/lo split (elementwise)
// ---------------------------------------------------------------------------
__global__ void split_kernel(const float* __restrict__ in,
                             __nv_bfloat16* __restrict__ oh, __nv_bfloat16* __restrict__ ol,
                             long long n)
{
    long long i = (long long)blockIdx.x * blockDim.x + threadIdx.x;
    long long stride = (long long)gridDim.x * blockDim.x;
    for (; i < n; i += stride) {
        float v = in[i];
        __nv_bfloat16 h = __float2bfloat16(v);
        oh[i] = h;
        ol[i] = __float2bfloat16(v - __bfloat162float(h));
    }
}

// ---------------------------------------------------------------------------
// Transpose + split: fp32 [R][C] (ldin) -> pair [C][R] (ldout), per z.
// ---------------------------------------------------------------------------
__global__ void tsplit_kernel(const float* __restrict__ in,
                              __nv_bfloat16* __restrict__ oh, __nv_bfloat16* __restrict__ ol,
                              int ldin, int ldout, long long inStride, long long outStride)
{
    __shared__ float t[32][33];
    in += (long long)blockIdx.z * inStride;
    oh += (long long)blockIdx.z * outStride;
    ol += (long long)blockIdx.z * outStride;
    const int c0 = blockIdx.x * 32, r0 = blockIdx.y * 32;
    const int tx = threadIdx.x & 31, ty = threadIdx.x >> 5;
#pragma unroll
    for (int j = 0; j < 4; j++)
        t[ty + j * 8][tx] = in[(long long)(r0 + ty + j * 8) * ldin + c0 + tx];
    __syncthreads();
#pragma unroll
    for (int j = 0; j < 4; j++) {
        float v = t[tx][ty + j * 8];
        __nv_bfloat16 h = __float2bfloat16(v);
        long long o = (long long)(c0 + ty + j * 8) * ldout + r0 + tx;
        oh[o] = h;
        ol[o] = __float2bfloat16(v - __bfloat162float(h));
    }
}

// ---------------------------------------------------------------------------
// V transpose: qkv pair -> vt pair [z][DHH][SS].
// ---------------------------------------------------------------------------
__global__ void vtrans_kernel(const __nv_bfloat16* __restrict__ qH,
                              const __nv_bfloat16* __restrict__ qL,
                              __nv_bfloat16* __restrict__ vH, __nv_bfloat16* __restrict__ vL)
{
    __shared__ __nv_bfloat16 tH[32][33], tL[32][33];
    const int zc = blockIdx.z, zbb = zc / HH, zhh = zc % HH;
    const __nv_bfloat16* bH = qH + (long long)(zbb * SS) * D3 + 2 * DD + zhh * DHH;
    const __nv_bfloat16* bL = qL + (long long)(zbb * SS) * D3 + 2 * DD + zhh * DHH;
    const int t0 = blockIdx.x * 32, d0 = blockIdx.y * 32;
    const int tx = threadIdx.x & 31, ty = threadIdx.x >> 5;
#pragma unroll
    for (int j = 0; j < 4; j++) {
        long long src = (long long)(t0 + ty + j * 8) * D3 + d0 + tx;
        tH[ty + j * 8][tx] = bH[src];
        tL[ty + j * 8][tx] = bL[src];
    }
    __syncthreads();
    __nv_bfloat16* oH = vH + (long long)zc * DHH * SS;
    __nv_bfloat16* oL = vL + (long long)zc * DHH * SS;
#pragma unroll
    for (int j = 0; j < 4; j++) {
        long long dst = (long long)(d0 + ty + j * 8) * SS + t0 + tx;
        oH[dst] = tH[tx][ty + j * 8];
        oL[dst] = tL[tx][ty + j * 8];
    }
}

// ---------------------------------------------------------------------------
// out = LN(a + b [+ gates@b2]) * g + beta ; optional bf16 pair output;
// optional fused MoE gate: gatesOut = softmax(out @ gw^T + gb).
// ---------------------------------------------------------------------------
__global__ void ln_kernel(const float* __restrict__ a, const float* __restrict__ b,
                          const float* __restrict__ g, const float* __restrict__ beta,
                          float* __restrict__ outF,
                          __nv_bfloat16* __restrict__ oh, __nv_bfloat16* __restrict__ ol,
                          const float* __restrict__ gates, const float* __restrict__ b2,
                          const float* __restrict__ gw, const float* __restrict__ gb,
                          float* __restrict__ gatesOut)
{
    long long row = blockIdx.x;
    const float* ar = a + row * DD;
    const float* br = b + row * DD;
    __shared__ float red[256];
    __shared__ float gpart[8][EE];
    __shared__ float gsum[EE];
    int tid = threadIdx.x;
    int wrp = tid >> 5, lane = tid & 31;

    float gt[EE];
    if (gates) {
#pragma unroll
        for (int e = 0; e < EE; e++) gt[e] = gates[row * EE + e];
    }

    float v[4]; float s = 0.f;
#pragma unroll
    for (int i = 0; i < 4; i++) {
        int c = tid + i * 256;
        float x = ar[c] + br[c];
        if (gates) {
            float s2 = 0.f;
#pragma unroll
            for (int e = 0; e < EE; e++) s2 += gt[e] * b2[e * DD + c];
            x += s2;
        }
        v[i] = x; s += x;
    }
    red[tid] = s; __syncthreads();
    for (int t = 128; t; t >>= 1) { if (tid < t) red[tid] += red[tid + t]; __syncthreads(); }
    float mean = red[0] * (1.f / DD); __syncthreads();

    float sq = 0.f;
#pragma unroll
    for (int i = 0; i < 4; i++) { float d = v[i] - mean; sq += d * d; }
    red[tid] = sq; __syncthreads();
    for (int t = 128; t; t >>= 1) { if (tid < t) red[tid] += red[tid + t]; __syncthreads(); }
    float inv = rsqrtf(red[0] * (1.f / DD) + 1e-5f);

    float o4[4];
#pragma unroll
    for (int i = 0; i < 4; i++) {
        int c = tid + i * 256;
        float o = (v[i] - mean) * inv * g[c] + beta[c];
        o4[i] = o;
        outF[row * DD + c] = o;
        if (oh) {
            __nv_bfloat16 h = __float2bfloat16(o);
            oh[row * DD + c] = h;
            ol[row * DD + c] = __float2bfloat16(o - __bfloat162float(h));
        }
    }

    // ---- fused gate: softmax(o @ gw^T + gb) ----
    if (gw) {
        float p[EE];
#pragma unroll
        for (int e = 0; e < EE; e++) p[e] = 0.f;
#pragma unroll
        for (int i = 0; i < 4; i++) {
            int c = tid + i * 256;
            float ov = o4[i];
#pragma unroll
            for (int e = 0; e < EE; e++) p[e] += ov * gw[e * DD + c];
        }
#pragma unroll
        for (int e = 0; e < EE; e++)
            for (int off = 16; off; off >>= 1)
                p[e] += __shfl_xor_sync(0xffffffff, p[e], off);
        if (lane == 0) {
#pragma unroll
            for (int e = 0; e < EE; e++) gpart[wrp][e] = p[e];
        }
        __syncthreads();
        if (tid < EE) {
            float sg = 0.f;
#pragma unroll
            for (int wq = 0; wq < 8; wq++) sg += gpart[wq][tid];
            gsum[tid] = sg + gb[tid];
        }
        __syncthreads();
        if (tid == 0) {
            float mx = -3.4e38f;
#pragma unroll
            for (int e = 0; e < EE; e++) mx = fmaxf(mx, gsum[e]);
            float sm = 0.f;
            float pe[EE];
#pragma unroll
            for (int e = 0; e < EE; e++) { pe[e] = expf(gsum[e] - mx); sm += pe[e]; }
            float invs = 1.f / sm;
#pragma unroll
            for (int e = 0; e < EE; e++) gatesOut[row * EE + e] = pe[e] * invs;
        }
    }
}

// ---------------------------------------------------------------------------
// Host orchestration (graph-capturable: launches only).
// ---------------------------------------------------------------------------
extern "C" void kernel_launch(void* const* d_in, const int* in_sizes, int n_in,
                              void* d_out, int out_size)
{
    const float* src        = (const float*)d_in[0];
    const float* in_proj_w  = (const float*)d_in[2];
    const float* in_proj_b  = (const float*)d_in[3];
    const float* out_proj_w = (const float*)d_in[4];
    const float* out_proj_b = (const float*)d_in[5];
    const float* gate_w     = (const float*)d_in[6];
    const float* gate_b     = (const float*)d_in[7];
    const float* w1         = (const float*)d_in[8];
    const float* b1         = (const float*)d_in[9];
    const float* w2         = (const float*)d_in[10];
    const float* b2         = (const float*)d_in[11];
    const float* ln1_g      = (const float*)d_in[12];
    const float* ln1_b      = (const float*)d_in[13];
    const float* ln2_g      = (const float*)d_in[14];
    const float* ln2_b      = (const float*)d_in[15];
    float* out = (float*)d_out;

    float *attn, *x, *ff, *gates;
    cudaGetSymbolAddress((void**)&attn,   g_attn);
    cudaGetSymbolAddress((void**)&x,      g_x);
    cudaGetSymbolAddress((void**)&ff,     g_ff);
    cudaGetSymbolAddress((void**)&gates,  g_gates);

    __nv_bfloat16 *srcH,*srcL,*wqH,*wqL,*woH,*woL,*w1H,*w1L,*w2H,*w2L;
    __nv_bfloat16 *qkvH,*qkvL,*vtH,*vtL,*ctxH,*ctxL,*xH,*xL,*hH,*hL;
    cudaGetSymbolAddress((void**)&srcH, g_srcH); cudaGetSymbolAddress((void**)&srcL, g_srcL);
    cudaGetSymbolAddress((void**)&wqH,  g_wqH);  cudaGetSymbolAddress((void**)&wqL,  g_wqL);
    cudaGetSymbolAddress((void**)&woH,  g_woH);  cudaGetSymbolAddress((void**)&woL,  g_woL);
    cudaGetSymbolAddress((void**)&w1H,  g_w1H);  cudaGetSymbolAddress((void**)&w1L,  g_w1L);
    cudaGetSymbolAddress((void**)&w2H,  g_w2H);  cudaGetSymbolAddress((void**)&w2L,  g_w2L);
    cudaGetSymbolAddress((void**)&qkvH, g_qkvH); cudaGetSymbolAddress((void**)&qkvL, g_qkvL);
    cudaGetSymbolAddress((void**)&vtH,  g_vtH);  cudaGetSymbolAddress((void**)&vtL,  g_vtL);
    cudaGetSymbolAddress((void**)&ctxH, g_ctxH); cudaGetSymbolAddress((void**)&ctxL, g_ctxL);
    cudaGetSymbolAddress((void**)&xH,   g_xH);   cudaGetSymbolAddress((void**)&xL,   g_xL);
    cudaGetSymbolAddress((void**)&hH,   g_hH);   cudaGetSymbolAddress((void**)&hL,   g_hL);

    const int SM128 = 2 * (2 * 10240 + 2 * 128 * 80);           // 81920
    const int SMFA  = 2 * 18432 + 2 * (2 * 18432 + 2 * 17408);  // 180224
    cudaFuncSetAttribute(mma_gemm<128,false,false,true >, cudaFuncAttributeMaxDynamicSharedMemorySize, SM128);
    cudaFuncSetAttribute(mma_gemm<128,false,false,false>, cudaFuncAttributeMaxDynamicSharedMemorySize, SM128);
    cudaFuncSetAttribute(mma_gemm<128,true ,true ,true >, cudaFuncAttributeMaxDynamicSharedMemorySize, SM128);
    cudaFuncSetAttribute(flash_kernel, cudaFuncAttributeMaxDynamicSharedMemorySize, SMFA);

    dim3 blk(256);

    // ---- conversions ----
    split_kernel<<<2048, 256>>>(src,        srcH, srcL, (long long)NTOK * DD);
    split_kernel<<<2048, 256>>>(in_proj_w,  wqH,  wqL,  (long long)D3 * DD);
    split_kernel<<<1024, 256>>>(out_proj_w, woH,  woL,  (long long)DD * DD);
    tsplit_kernel<<<dim3(FFF/32, DD/32, EE), blk>>>(w1, w1H, w1L, FFF, DD,
        (long long)DD * FFF, (long long)FFF * DD);
    tsplit_kernel<<<dim3(DD/32, FFF/32, EE), blk>>>(w2, w2H, w2L, DD, EFF,
        (long long)FFF * DD, (long long)FFF);

    // ---- 1. qkv pair = src @ in_proj_w^T + b ----
    mma_gemm<128,false,false,true><<<dim3(D3/128, NTOK/128, 1), blk, SM128>>>(
        srcH, srcL, wqH, wqL, nullptr, qkvH, qkvL,
        DD, DD, DD, D3, 1, 0,0, 0,0, 0,0, in_proj_b, nullptr, 1.f);

    // ---- 2. v transpose ----
    vtrans_kernel<<<dim3(SS/32, DHH/32, BB*HH), blk>>>(qkvH, qkvL, vtH, vtL);

    // ---- 3. flash attention -> ctx pair ----
    flash_kernel<<<dim3(SS/128, 1, BB*HH), blk, SMFA>>>(
        qkvH, qkvL, vtH, vtL, ctxH, ctxL);

    // ---- 4. attn = ctx @ out_proj_w^T + b (fp32) ----
    mma_gemm<128,false,false,false><<<dim3(DD/128, NTOK/128, 1), blk, SM128>>>(
        ctxH, ctxL, woH, woL, attn, nullptr, nullptr,
        DD, DD, DD, DD, 1, 0,0, 0,0, 0,0, out_proj_b, nullptr, 1.f);

    // ---- 5. x = LN1(src + attn), fp32 + pair + fused gate ----
    ln_kernel<<<NTOK, blk>>>(src, attn, ln1_g, ln1_b, x, xH, xL, nullptr, nullptr,
                             gate_w, gate_b, gates);

    // ---- 6. h' pair = gate * relu(x @ w1t^T + b1)   [4096, 16384] ----
    mma_gemm<128,true,true,true><<<dim3(EFF/128, NTOK/128, 1), blk, SM128>>>(
        xH, xL, w1H, w1L, nullptr, hH, hL,
        DD, DD, DD, EFF, 1, 0,0, 0,0, 0,0, b1, gates, 1.f);

    // ---- 7. ff = h' @ w2t^T (fp32), K=16384 ----
    mma_gemm<128,false,false,false><<<dim3(DD/128, NTOK/128, 1), blk, SM128>>>(
        hH, hL, w2H, w2L, ff, nullptr, nullptr,
        EFF, EFF, EFF, DD, 1, 0,0, 0,0, 0,0, nullptr, nullptr, 1.f);

    // ---- 8. out = LN2(x + ff + gates@b2) ----
    ln_kernel<<<NTOK, blk>>>(x, ff, ln2_g, ln2_b, out, nullptr, nullptr, gates, b2,
                             nullptr, nullptr, nullptr);
}

// round 9
// speedup vs baseline: 2.2009x; 1.9670x over previous
#include <cuda_runtime.h>
#include <cuda_bf16.h>
#include <cuda_fp16.h>

#define BB 4
#define SS 1024
#define DD 1024
#define HH 16
#define DHH 64
#define EE 8
#define FFF 2048
#define NTOK (BB*SS)
#define D3 (3*DD)
#define EFF (EE*FFF)

// ---------------------------------------------------------------------------
// Scratch (static device globals — allocations are forbidden).
// ---------------------------------------------------------------------------
__device__ float g_attn[(size_t)NTOK*DD];
__device__ float g_x[(size_t)NTOK*DD];
__device__ float g_ff[(size_t)NTOK*DD];
__device__ float g_gates[(size_t)NTOK*EE];

__device__ __nv_bfloat16 g_srcH[(size_t)NTOK*DD],  g_srcL[(size_t)NTOK*DD];
__device__ __nv_bfloat16 g_wqH[(size_t)D3*DD],     g_wqL[(size_t)D3*DD];
__device__ __nv_bfloat16 g_woH[(size_t)DD*DD],     g_woL[(size_t)DD*DD];
__device__ __nv_bfloat16 g_qkvH[(size_t)NTOK*D3],  g_qkvL[(size_t)NTOK*D3];
__device__ __nv_bfloat16 g_vtH[(size_t)BB*HH*DHH*SS], g_vtL[(size_t)BB*HH*DHH*SS];
__device__ __nv_bfloat16 g_ctxH[(size_t)NTOK*DD],  g_ctxL[(size_t)NTOK*DD];

__device__ __half g_xT[(size_t)NTOK*DD];       // fp16 x for MoE
__device__ __half g_w1T[(size_t)EFF*DD];       // fp16 w1 transposed [EFF][DD]
__device__ __half g_w2T[(size_t)DD*EFF];       // fp16 w2 transposed [DD][EFF]
__device__ __half g_hT[(size_t)NTOK*EFF];      // fp16 h' [NTOK][EFF]

// ---------------------------------------------------------------------------
// PTX helpers (sm_80-era instructions only — legal on plain sm_103 target).
// ---------------------------------------------------------------------------
__device__ __forceinline__ unsigned smem_u32(const void* p){
    unsigned a;
    asm("{ .reg .u64 t; cvta.to.shared.u64 t, %1; cvt.u32.u64 %0, t; }" : "=r"(a) : "l"(p));
    return a;
}
__device__ __forceinline__ void cp16(unsigned saddr, const void* gaddr){
    asm volatile("cp.async.cg.shared.global [%0], [%1], 16;" :: "r"(saddr), "l"(gaddr));
}
#define CP_COMMIT() asm volatile("cp.async.commit_group;" ::: "memory")
template<int N> __device__ __forceinline__ void cp_wait(){
    asm volatile("cp.async.wait_group %0;" :: "n"(N) : "memory");
}
__device__ __forceinline__ void ldsm_x4(unsigned addr, unsigned* r){
    asm volatile("ldmatrix.sync.aligned.m8n8.x4.shared.b16 {%0,%1,%2,%3}, [%4];"
        : "=r"(r[0]),"=r"(r[1]),"=r"(r[2]),"=r"(r[3]) : "r"(addr));
}
__device__ __forceinline__ void mma16816(float* c, const unsigned* a, const unsigned* b){
    asm volatile("mma.sync.aligned.m16n8k16.row.col.f32.bf16.bf16.f32 "
        "{%0,%1,%2,%3}, {%4,%5,%6,%7}, {%8,%9}, {%0,%1,%2,%3};"
        : "+f"(c[0]),"+f"(c[1]),"+f"(c[2]),"+f"(c[3])
        : "r"(a[0]),"r"(a[1]),"r"(a[2]),"r"(a[3]), "r"(b[0]),"r"(b[1]));
}
__device__ __forceinline__ void mma16816h(float* c, const unsigned* a, const unsigned* b){
    asm volatile("mma.sync.aligned.m16n8k16.row.col.f32.f16.f16.f32 "
        "{%0,%1,%2,%3}, {%4,%5,%6,%7}, {%8,%9}, {%0,%1,%2,%3};"
        : "+f"(c[0]),"+f"(c[1]),"+f"(c[2]),"+f"(c[3])
        : "r"(a[0]),"r"(a[1]),"r"(a[2]),"r"(a[3]), "r"(b[0]),"r"(b[1]));
}
__device__ __forceinline__ unsigned packbf2(float lo, float hi){
    __nv_bfloat162 t = __floats2bfloat162_rn(lo, hi);
    return *reinterpret_cast<unsigned*>(&t);
}

// ---------------------------------------------------------------------------
// bf16x3 split GEMM via mma.sync (attention path). BM=128, BN=128, BK=32.
// ---------------------------------------------------------------------------
template<int BN, bool OUTPAIR>
__global__ void __launch_bounds__(256, 2) mma_gemm(
    const __nv_bfloat16* __restrict__ Ahi, const __nv_bfloat16* __restrict__ Alo,
    const __nv_bfloat16* __restrict__ Bhi, const __nv_bfloat16* __restrict__ Blo,
    float* __restrict__ C, __nv_bfloat16* __restrict__ Chi, __nv_bfloat16* __restrict__ Clo,
    int K, int lda, int ldb, int ldc, int Hbatch,
    long long aSB, long long aSH, long long bSB, long long bSH,
    long long cSB, long long cSH,
    const float* __restrict__ bias, float alpha)
{
    constexpr int WX = BN / 32;
    constexpr int WY = 8 / WX;
    constexpr int WM = 128 / WY;
    constexpr int MF = WM / 16;
    constexpr int NF = 4;
    constexpr unsigned APITCH = 80u;
    constexpr unsigned ABYTES = 128u * APITCH;
    constexpr unsigned BNB    = (unsigned)BN * APITCH;
    constexpr unsigned STAGE  = 2u * ABYTES + 2u * BNB;

    extern __shared__ char smem[];
    const unsigned sb = smem_u32(smem);
    const int tid = threadIdx.x, w = tid >> 5, lane = tid & 31;
    const int wy = w / WX, wx = w % WX;
    const int wm0 = wy * WM, wn0 = wx * 32;

    const int z  = blockIdx.z;
    const int zb = z / Hbatch, zh = z % Hbatch;
    Ahi += zb * aSB + zh * aSH;  Alo += zb * aSB + zh * aSH;
    Bhi += zb * bSB + zh * bSH;  Blo += zb * bSB + zh * bSH;
    if (OUTPAIR) { Chi += zb * cSB + zh * cSH; Clo += zb * cSB + zh * cSH; }
    else         { C   += zb * cSB + zh * cSH; }

    const int row0 = blockIdx.y * 128;
    const int col0 = blockIdx.x * BN;
    const int NC = K >> 5;

    auto loadChunk = [&](int c, int s){
        const unsigned st = sb + (unsigned)s * STAGE;
        for (int i = tid; i < 512; i += 256) {
            int r = i >> 2, ch = i & 3;
            unsigned so = st + (unsigned)r * APITCH + (unsigned)ch * 16u;
            const char* gH = (const char*)(Ahi + (long long)(row0 + r) * lda + c * 32) + ch * 16;
            const char* gL = (const char*)(Alo + (long long)(row0 + r) * lda + c * 32) + ch * 16;
            cp16(so, gH);
            cp16(so + ABYTES, gL);
        }
        for (int i = tid; i < BN * 4; i += 256) {
            int r = i >> 2, ch = i & 3;
            unsigned so = st + 2u * ABYTES + (unsigned)r * APITCH + (unsigned)ch * 16u;
            const char* gH = (const char*)(Bhi + (long long)(col0 + r) * ldb + c * 32) + ch * 16;
            const char* gL = (const char*)(Blo + (long long)(col0 + r) * ldb + c * 32) + ch * 16;
            cp16(so, gH);
            cp16(so + BNB, gL);
        }
        CP_COMMIT();
    };

    float cr[MF][NF][4];
#pragma unroll
    for (int i = 0; i < MF; i++)
#pragma unroll
        for (int j = 0; j < NF; j++)
#pragma unroll
            for (int q = 0; q < 4; q++) cr[i][j][q] = 0.f;

    loadChunk(0, 0);

    for (int c = 0; c < NC; c++) {
        if (c + 1 < NC) { loadChunk(c + 1, (c + 1) & 1); cp_wait<1>(); }
        else            { cp_wait<0>(); }
        __syncthreads();

        const unsigned st  = sb + (unsigned)(c & 1) * STAGE;
        const unsigned aHB = st;
        const unsigned aLB = st + ABYTES;
        const unsigned bHB = st + 2u * ABYTES;
        const unsigned bLB = st + 2u * ABYTES + BNB;

#pragma unroll
        for (int ks = 0; ks < 2; ks++) {
            const unsigned aRow = (unsigned)(wm0 + (lane & 15)) * APITCH
                                + (unsigned)(ks * 2 + (lane >> 4)) * 16u;
            const unsigned bRow = (unsigned)(wn0 + (lane & 7) + ((lane >> 4) << 3)) * APITCH
                                + (unsigned)(ks * 2 + ((lane >> 3) & 1)) * 16u;

            unsigned aF[MF][4];
#pragma unroll
            for (int mf = 0; mf < MF; mf++)
                ldsm_x4(aHB + aRow + (unsigned)(mf * 16) * APITCH, aF[mf]);

            unsigned bH[NF][2], bL[NF][2];
#pragma unroll
            for (int nfp = 0; nfp < NF/2; nfp++) {
                unsigned off = bRow + (unsigned)(nfp * 16) * APITCH;
                unsigned t[4];
                ldsm_x4(bHB + off, t);
                bH[nfp*2][0] = t[0]; bH[nfp*2][1] = t[1];
                bH[nfp*2+1][0] = t[2]; bH[nfp*2+1][1] = t[3];
                ldsm_x4(bLB + off, t);
                bL[nfp*2][0] = t[0]; bL[nfp*2][1] = t[1];
                bL[nfp*2+1][0] = t[2]; bL[nfp*2+1][1] = t[3];
            }

#pragma unroll
            for (int mf = 0; mf < MF; mf++)
#pragma unroll
                for (int nf = 0; nf < NF; nf++)
                    mma16816(cr[mf][nf], aF[mf], bH[nf]);
#pragma unroll
            for (int mf = 0; mf < MF; mf++)
#pragma unroll
                for (int nf = 0; nf < NF; nf++)
                    mma16816(cr[mf][nf], aF[mf], bL[nf]);

#pragma unroll
            for (int mf = 0; mf < MF; mf++)
                ldsm_x4(aLB + aRow + (unsigned)(mf * 16) * APITCH, aF[mf]);
#pragma unroll
            for (int mf = 0; mf < MF; mf++)
#pragma unroll
                for (int nf = 0; nf < NF; nf++)
                    mma16816(cr[mf][nf], aF[mf], bH[nf]);
        }
        __syncthreads();
    }

    // ---- epilogue: stage in smem, coalesced copy ----
    constexpr unsigned PP = (unsigned)BN * 2u + 16u;
    constexpr unsigned PF = (unsigned)BN * 4u + 16u;

#pragma unroll
    for (int mf = 0; mf < MF; mf++) {
        const int ml = wm0 + mf * 16 + (lane >> 2);
#pragma unroll
        for (int nf = 0; nf < NF; nf++) {
            const int nl = wn0 + nf * 8 + (lane & 3) * 2;
            const int n  = col0 + nl;
            float a0 = cr[mf][nf][0], a1 = cr[mf][nf][1];
            float b0 = cr[mf][nf][2], b1 = cr[mf][nf][3];
            a0 *= alpha; a1 *= alpha; b0 *= alpha; b1 *= alpha;
            if (bias) { float bb0 = bias[n], bb1 = bias[n+1]; a0 += bb0; a1 += bb1; b0 += bb0; b1 += bb1; }
            if (OUTPAIR) {
                __nv_bfloat162 hh0 = __floats2bfloat162_rn(a0, a1);
                __nv_bfloat162 ll0 = __floats2bfloat162_rn(a0 - __bfloat162float(hh0.x),
                                                           a1 - __bfloat162float(hh0.y));
                __nv_bfloat162 hh1 = __floats2bfloat162_rn(b0, b1);
                __nv_bfloat162 ll1 = __floats2bfloat162_rn(b0 - __bfloat162float(hh1.x),
                                                           b1 - __bfloat162float(hh1.y));
                *reinterpret_cast<__nv_bfloat162*>(smem + (unsigned)ml * PP + (unsigned)nl * 2u) = hh0;
                *reinterpret_cast<__nv_bfloat162*>(smem + 128u*PP + (unsigned)ml * PP + (unsigned)nl * 2u) = ll0;
                *reinterpret_cast<__nv_bfloat162*>(smem + (unsigned)(ml+8) * PP + (unsigned)nl * 2u) = hh1;
                *reinterpret_cast<__nv_bfloat162*>(smem + 128u*PP + (unsigned)(ml+8) * PP + (unsigned)nl * 2u) = ll1;
            } else {
                *reinterpret_cast<float2*>(smem + (unsigned)ml * PF + (unsigned)nl * 4u) = make_float2(a0, a1);
                *reinterpret_cast<float2*>(smem + (unsigned)(ml+8) * PF + (unsigned)nl * 4u) = make_float2(b0, b1);
            }
        }
    }
    __syncthreads();

    if (OUTPAIR) {
        constexpr int CH = BN / 8;
        for (int i = tid; i < 128 * CH; i += 256) {
            int r = i / CH, ch = i % CH;
            uint4 hv = *reinterpret_cast<uint4*>(smem + (unsigned)r * PP + (unsigned)ch * 16u);
            uint4 lv = *reinterpret_cast<uint4*>(smem + 128u*PP + (unsigned)r * PP + (unsigned)ch * 16u);
            long long base = (long long)(row0 + r) * ldc + col0 + ch * 8;
            *reinterpret_cast<uint4*>(Chi + base) = hv;
            *reinterpret_cast<uint4*>(Clo + base) = lv;
        }
    } else {
        constexpr int CHF = BN / 4;
        for (int i = tid; i < 128 * CHF; i += 256) {
            int r = i / CHF, ch = i % CHF;
            uint4 v = *reinterpret_cast<uint4*>(smem + (unsigned)r * PF + (unsigned)ch * 16u);
            long long base = (long long)(row0 + r) * ldc + col0 + ch * 4;
            *reinterpret_cast<uint4*>(C + base) = v;
        }
    }
}

// ---------------------------------------------------------------------------
// fp16 single-pass GEMM (MoE path).  C = epi( A @ B^T ), A [M,K] half (lda),
// B [N,K] half (ldb). BM=128, BN=128, BK=64, warp tile 64x32, 2 CTAs/SM.
// ---------------------------------------------------------------------------
template<bool RELU, bool GATE, bool OUTHALF>
__global__ void __launch_bounds__(256, 2) mma_gemm_f16(
    const __half* __restrict__ A, const __half* __restrict__ Bm,
    float* __restrict__ C, __half* __restrict__ Ch,
    int K, int lda, int ldb, int ldc,
    const float* __restrict__ bias, const float* __restrict__ gates)
{
    constexpr int BN = 128;
    constexpr int MF = 4;                 // warp tile 64x32
    constexpr int NF = 4;
    constexpr unsigned APITCH = 144u;     // 128B row + 16B pad
    constexpr unsigned ABYTES = 128u * APITCH;       // 18432
    constexpr unsigned BNB    = 128u * APITCH;       // 18432
    constexpr unsigned STAGE  = ABYTES + BNB;        // 36864

    extern __shared__ char smem[];
    const unsigned sb = smem_u32(smem);
    const int tid = threadIdx.x, w = tid >> 5, lane = tid & 31;
    const int wy = w >> 2, wx = w & 3;
    const int wm0 = wy * 64, wn0 = wx * 32;

    const int row0 = blockIdx.y * 128;
    const int col0 = blockIdx.x * BN;
    const int NC = K >> 6;

    auto loadChunk = [&](int c, int s){
        const unsigned st = sb + (unsigned)s * STAGE;
        for (int i = tid; i < 1024; i += 256) {
            int r = i >> 3, ch = i & 7;
            unsigned so = st + (unsigned)r * APITCH + (unsigned)ch * 16u;
            cp16(so, (const char*)(A + (long long)(row0 + r) * lda + c * 64) + ch * 16);
        }
        for (int i = tid; i < 1024; i += 256) {
            int r = i >> 3, ch = i & 7;
            unsigned so = st + ABYTES + (unsigned)r * APITCH + (unsigned)ch * 16u;
            cp16(so, (const char*)(Bm + (long long)(col0 + r) * ldb + c * 64) + ch * 16);
        }
        CP_COMMIT();
    };

    float cr[MF][NF][4];
#pragma unroll
    for (int i = 0; i < MF; i++)
#pragma unroll
        for (int j = 0; j < NF; j++)
#pragma unroll
            for (int q = 0; q < 4; q++) cr[i][j][q] = 0.f;

    loadChunk(0, 0);

    for (int c = 0; c < NC; c++) {
        if (c + 1 < NC) { loadChunk(c + 1, (c + 1) & 1); cp_wait<1>(); }
        else            { cp_wait<0>(); }
        __syncthreads();

        const unsigned st = sb + (unsigned)(c & 1) * STAGE;
        const unsigned aB = st, bB = st + ABYTES;

#pragma unroll
        for (int ks = 0; ks < 4; ks++) {
            const unsigned aRow = (unsigned)(wm0 + (lane & 15)) * APITCH
                                + (unsigned)(ks * 32) + (unsigned)((lane >> 4) * 16);
            const unsigned bRow = (unsigned)(wn0 + (lane & 7) + ((lane >> 4) << 3)) * APITCH
                                + (unsigned)(ks * 32) + (unsigned)(((lane >> 3) & 1) * 16);

            unsigned aF[MF][4];
#pragma unroll
            for (int mf = 0; mf < MF; mf++)
                ldsm_x4(aB + aRow + (unsigned)(mf * 16) * APITCH, aF[mf]);

            unsigned bF[NF][2];
#pragma unroll
            for (int nfp = 0; nfp < 2; nfp++) {
                unsigned t[4];
                ldsm_x4(bB + bRow + (unsigned)(nfp * 16) * APITCH, t);
                bF[nfp*2][0] = t[0]; bF[nfp*2][1] = t[1];
                bF[nfp*2+1][0] = t[2]; bF[nfp*2+1][1] = t[3];
            }

#pragma unroll
            for (int mf = 0; mf < MF; mf++)
#pragma unroll
                for (int nf = 0; nf < NF; nf++)
                    mma16816h(cr[mf][nf], aF[mf], bF[nf]);
        }
        __syncthreads();
    }

    // ---- epilogue: stage in smem, coalesced copy ----
    constexpr unsigned PH = (unsigned)BN * 2u + 16u;   // half pitch 272
    constexpr unsigned PF = (unsigned)BN * 4u + 16u;   // fp32 pitch 528

#pragma unroll
    for (int mf = 0; mf < MF; mf++) {
        const int ml = wm0 + mf * 16 + (lane >> 2);
#pragma unroll
        for (int nf = 0; nf < NF; nf++) {
            const int nl = wn0 + nf * 8 + (lane & 3) * 2;
            const int n  = col0 + nl;
            float a0 = cr[mf][nf][0], a1 = cr[mf][nf][1];
            float b0 = cr[mf][nf][2], b1 = cr[mf][nf][3];
            if (bias) { float bb0 = bias[n], bb1 = bias[n+1]; a0 += bb0; a1 += bb1; b0 += bb0; b1 += bb1; }
            if (RELU) { a0 = fmaxf(a0,0.f); a1 = fmaxf(a1,0.f); b0 = fmaxf(b0,0.f); b1 = fmaxf(b1,0.f); }
            if (GATE) {
                float g0 = gates[(long long)(row0+ml) * EE + (n / FFF)];
                float g1 = gates[(long long)(row0+ml+8) * EE + (n / FFF)];
                a0 *= g0; a1 *= g0; b0 *= g1; b1 *= g1;
            }
            if (OUTHALF) {
                *reinterpret_cast<__half2*>(smem + (unsigned)ml * PH + (unsigned)nl * 2u)
                    = __floats2half2_rn(a0, a1);
                *reinterpret_cast<__half2*>(smem + (unsigned)(ml+8) * PH + (unsigned)nl * 2u)
                    = __floats2half2_rn(b0, b1);
            } else {
                *reinterpret_cast<float2*>(smem + (unsigned)ml * PF + (unsigned)nl * 4u) = make_float2(a0, a1);
                *reinterpret_cast<float2*>(smem + (unsigned)(ml+8) * PF + (unsigned)nl * 4u) = make_float2(b0, b1);
            }
        }
    }
    __syncthreads();

    if (OUTHALF) {
        constexpr int CH = BN / 8;
        for (int i = tid; i < 128 * CH; i += 256) {
            int r = i / CH, ch = i % CH;
            uint4 v = *reinterpret_cast<uint4*>(smem + (unsigned)r * PH + (unsigned)ch * 16u);
            *reinterpret_cast<uint4*>(Ch + (long long)(row0 + r) * ldc + col0 + ch * 8) = v;
        }
    } else {
        constexpr int CHF = BN / 4;
        for (int i = tid; i < 128 * CHF; i += 256) {
            int r = i / CHF, ch = i % CHF;
            uint4 v = *reinterpret_cast<uint4*>(smem + (unsigned)r * PF + (unsigned)ch * 16u);
            *reinterpret_cast<uint4*>(C + (long long)(row0 + r) * ldc + col0 + ch * 4) = v;
        }
    }
}

// ---------------------------------------------------------------------------
// Flash attention (unchanged from R8).
// ---------------------------------------------------------------------------
__global__ void __launch_bounds__(256) flash_kernel(
    const __nv_bfloat16* __restrict__ qkvH, const __nv_bfloat16* __restrict__ qkvL,
    const __nv_bfloat16* __restrict__ vtH,  const __nv_bfloat16* __restrict__ vtL,
    __nv_bfloat16* __restrict__ cH, __nv_bfloat16* __restrict__ cL)
{
    constexpr unsigned QP = 144u, VP = 272u;
    constexpr unsigned QBYTES = 128u * QP;
    constexpr unsigned KBYTES = 128u * QP;
    constexpr unsigned VBYTES = 64u * VP;
    constexpr unsigned STAGE  = 2u * KBYTES + 2u * VBYTES;

    extern __shared__ char smem[];
    const unsigned sb = smem_u32(smem);
    const int tid = threadIdx.x, w = tid >> 5, lane = tid & 31;

    const int bh = blockIdx.z, b = bh >> 4, h = bh & 15;
    const int q0 = blockIdx.x * 128;

    const __nv_bfloat16* Qh = qkvH + ((long long)b * SS) * D3 + h * DHH;
    const __nv_bfloat16* Ql = qkvL + ((long long)b * SS) * D3 + h * DHH;
    const __nv_bfloat16* Kh = Qh + DD;
    const __nv_bfloat16* Kl = Ql + DD;
    const __nv_bfloat16* Vh = vtH + (long long)bh * DHH * SS;
    const __nv_bfloat16* Vl = vtL + (long long)bh * DHH * SS;

    const unsigned qHB = sb, qLB = sb + QBYTES;
    const unsigned kvBase = sb + 2u * QBYTES;

    for (int i = tid; i < 1024; i += 256) {
        int r = i >> 3, ch = i & 7;
        unsigned so = (unsigned)r * QP + (unsigned)ch * 16u;
        cp16(qHB + so, (const char*)(Qh + (long long)(q0 + r) * D3) + ch * 16);
        cp16(qLB + so, (const char*)(Ql + (long long)(q0 + r) * D3) + ch * 16);
    }

    auto loadKV = [&](int t, int s){
        const unsigned st = kvBase + (unsigned)s * STAGE;
        const int k0 = t * 128;
        for (int i = tid; i < 1024; i += 256) {
            int r = i >> 3, ch = i & 7;
            unsigned so = st + (unsigned)r * QP + (unsigned)ch * 16u;
            cp16(so, (const char*)(Kh + (long long)(k0 + r) * D3) + ch * 16);
            cp16(so + KBYTES, (const char*)(Kl + (long long)(k0 + r) * D3) + ch * 16);
        }
        const unsigned vst = st + 2u * KBYTES;
        for (int i = tid; i < 1024; i += 256) {
            int r = i >> 4, ch = i & 15;
            unsigned so = vst + (unsigned)r * VP + (unsigned)ch * 16u;
            cp16(so, (const char*)(Vh + (long long)r * SS + k0) + ch * 16);
            cp16(so + VBYTES, (const char*)(Vl + (long long)r * SS + k0) + ch * 16);
        }
        CP_COMMIT();
    };
    loadKV(0, 0);

    float o[8][4];
#pragma unroll
    for (int i = 0; i < 8; i++)
#pragma unroll
        for (int q = 0; q < 4; q++) o[i][q] = 0.f;
    float m0 = -1e30f, m1 = -1e30f, l0 = 0.f, l1 = 0.f;
    const float scale = 0.125f;

    for (int t = 0; t < 8; t++) {
        if (t + 1 < 8) { loadKV(t + 1, (t + 1) & 1); cp_wait<1>(); }
        else           { cp_wait<0>(); }
        __syncthreads();

        const unsigned st  = kvBase + (unsigned)(t & 1) * STAGE;
        const unsigned kHB = st, kLB = st + KBYTES;
        const unsigned vHB = st + 2u * KBYTES, vLB = vHB + VBYTES;

        float sc[16][4];
#pragma unroll
        for (int i = 0; i < 16; i++)
#pragma unroll
            for (int q = 0; q < 4; q++) sc[i][q] = 0.f;

#pragma unroll
        for (int ks = 0; ks < 4; ks++) {
            const unsigned aRow = (unsigned)(w * 16 + (lane & 15)) * QP
                                + (unsigned)(ks * 2 + (lane >> 4)) * 16u;
            unsigned aH[4], aL[4];
            ldsm_x4(qHB + aRow, aH);
            ldsm_x4(qLB + aRow, aL);
#pragma unroll
            for (int nfp = 0; nfp < 8; nfp++) {
                const unsigned bo = (unsigned)(nfp * 16 + (lane & 7) + ((lane >> 4) << 3)) * QP
                                  + (unsigned)(ks * 2 + ((lane >> 3) & 1)) * 16u;
                unsigned tH[4], tL[4];
                ldsm_x4(kHB + bo, tH);
                ldsm_x4(kLB + bo, tL);
                mma16816(sc[nfp*2],   aH, tH);
                mma16816(sc[nfp*2+1], aH, tH + 2);
                mma16816(sc[nfp*2],   aL, tH);
                mma16816(sc[nfp*2+1], aL, tH + 2);
                mma16816(sc[nfp*2],   aH, tL);
                mma16816(sc[nfp*2+1], aH, tL + 2);
            }
        }

        float r0 = -1e30f, r1 = -1e30f;
#pragma unroll
        for (int i = 0; i < 16; i++) {
            r0 = fmaxf(r0, fmaxf(sc[i][0], sc[i][1]));
            r1 = fmaxf(r1, fmaxf(sc[i][2], sc[i][3]));
        }
        r0 = fmaxf(r0, __shfl_xor_sync(0xffffffff, r0, 1));
        r0 = fmaxf(r0, __shfl_xor_sync(0xffffffff, r0, 2));
        r1 = fmaxf(r1, __shfl_xor_sync(0xffffffff, r1, 1));
        r1 = fmaxf(r1, __shfl_xor_sync(0xffffffff, r1, 2));
        const float mn0 = fmaxf(m0, r0 * scale);
        const float mn1 = fmaxf(m1, r1 * scale);
        const float cor0 = __expf(m0 - mn0);
        const float cor1 = __expf(m1 - mn1);
        m0 = mn0; m1 = mn1;

        float s0 = 0.f, s1 = 0.f;
#pragma unroll
        for (int i = 0; i < 16; i++) {
            sc[i][0] = __expf(sc[i][0] * scale - m0);
            sc[i][1] = __expf(sc[i][1] * scale - m0);
            sc[i][2] = __expf(sc[i][2] * scale - m1);
            sc[i][3] = __expf(sc[i][3] * scale - m1);
            s0 += sc[i][0] + sc[i][1];
            s1 += sc[i][2] + sc[i][3];
        }
        s0 += __shfl_xor_sync(0xffffffff, s0, 1);
        s0 += __shfl_xor_sync(0xffffffff, s0, 2);
        s1 += __shfl_xor_sync(0xffffffff, s1, 1);
        s1 += __shfl_xor_sync(0xffffffff, s1, 2);
        l0 = l0 * cor0 + s0;
        l1 = l1 * cor1 + s1;
#pragma unroll
        for (int i = 0; i < 8; i++) {
            o[i][0] *= cor0; o[i][1] *= cor0;
            o[i][2] *= cor1; o[i][3] *= cor1;
        }

#pragma unroll
        for (int kv = 0; kv < 8; kv++) {
            float* p0 = sc[kv*2];
            float* p1 = sc[kv*2+1];
            unsigned aH[4], aL[4];
            {
                __nv_bfloat16 h00 = __float2bfloat16(p0[0]), h01 = __float2bfloat16(p0[1]);
                __nv_bfloat16 h02 = __float2bfloat16(p0[2]), h03 = __float2bfloat16(p0[3]);
                __nv_bfloat16 h10 = __float2bfloat16(p1[0]), h11 = __float2bfloat16(p1[1]);
                __nv_bfloat16 h12 = __float2bfloat16(p1[2]), h13 = __float2bfloat16(p1[3]);
                aH[0] = ((unsigned)__bfloat16_as_ushort(h01) << 16) | __bfloat16_as_ushort(h00);
                aH[1] = ((unsigned)__bfloat16_as_ushort(h03) << 16) | __bfloat16_as_ushort(h02);
                aH[2] = ((unsigned)__bfloat16_as_ushort(h11) << 16) | __bfloat16_as_ushort(h10);
                aH[3] = ((unsigned)__bfloat16_as_ushort(h13) << 16) | __bfloat16_as_ushort(h12);
                aL[0] = packbf2(p0[0] - __bfloat162float(h00), p0[1] - __bfloat162float(h01));
                aL[1] = packbf2(p0[2] - __bfloat162float(h02), p0[3] - __bfloat162float(h03));
                aL[2] = packbf2(p1[0] - __bfloat162float(h10), p1[1] - __bfloat162float(h11));
                aL[3] = packbf2(p1[2] - __bfloat162float(h12), p1[3] - __bfloat162float(h13));
            }
#pragma unroll
            for (int vf = 0; vf < 4; vf++) {
                const unsigned bo = (unsigned)(vf * 16 + (lane & 7) + ((lane >> 4) << 3)) * VP
                                  + (unsigned)(kv * 2 + ((lane >> 3) & 1)) * 16u;
                unsigned tH[4], tL[4];
                ldsm_x4(vHB + bo, tH);
                ldsm_x4(vLB + bo, tL);
                mma16816(o[vf*2],   aH, tH);
                mma16816(o[vf*2+1], aH, tH + 2);
                mma16816(o[vf*2],   aL, tH);
                mma16816(o[vf*2+1], aL, tH + 2);
                mma16816(o[vf*2],   aH, tL);
                mma16816(o[vf*2+1], aH, tL + 2);
            }
        }
        __syncthreads();
    }

    const float inv0 = 1.f / l0, inv1 = 1.f / l1;
    const int r = q0 + w * 16 + (lane >> 2);
    const long long tok0 = (long long)(b * SS + r);
    const long long tok1 = tok0 + 8;
#pragma unroll
    for (int nf = 0; nf < 8; nf++) {
        const int d = h * DHH + nf * 8 + (lane & 3) * 2;
#pragma unroll
        for (int q = 0; q < 2; q++) {
            float v0 = o[nf][q]     * inv0;
            float v1 = o[nf][2 + q] * inv1;
            __nv_bfloat16 h0 = __float2bfloat16(v0);
            __nv_bfloat16 h1 = __float2bfloat16(v1);
            cH[tok0 * DD + d + q] = h0;
            cL[tok0 * DD + d + q] = __float2bfloat16(v0 - __bfloat162float(h0));
            cH[tok1 * DD + d + q] = h1;
            cL[tok1 * DD + d + q] = __float2bfloat16(v1 - __bfloat162float(h1));
        }
    }
}

// ---------------------------------------------------------------------------
// fp32 -> bf16 hi/lo split (elementwise)
// ---------------------------------------------------------------------------
__global__ void split_kernel(const float* __restrict__ in,
                             __nv_bfloat16* __restrict__ oh, __nv_bfloat16* __restrict__ ol,
                             long long n)
{
    long long i = (long long)blockIdx.x * blockDim.x + threadIdx.x;
    long long stride = (long long)gridDim.x * blockDim.x;
    for (; i < n; i += stride) {
        float v = in[i];
        __nv_bfloat16 h = __float2bfloat16(v);
        oh[i] = h;
        ol[i] = __float2bfloat16(v - __bfloat162float(h));
    }
}

// ---------------------------------------------------------------------------
// Transpose + fp16: in fp32 [R][C] (ldin) -> half [C][R] (ldout), per z.
// ---------------------------------------------------------------------------
__global__ void thalf_kernel(const float* __restrict__ in, __half* __restrict__ ot,
                             int ldin, int ldout, long long inStride, long long outStride)
{
    __shared__ float t[32][33];
    in += (long long)blockIdx.z * inStride;
    ot += (long long)blockIdx.z * outStride;
    const int c0 = blockIdx.x * 32, r0 = blockIdx.y * 32;
    const int tx = threadIdx.x & 31, ty = threadIdx.x >> 5;
#pragma unroll
    for (int j = 0; j < 4; j++)
        t[ty + j * 8][tx] = in[(long long)(r0 + ty + j * 8) * ldin + c0 + tx];
    __syncthreads();
#pragma unroll
    for (int j = 0; j < 4; j++)
        ot[(long long)(c0 + ty + j * 8) * ldout + r0 + tx] = __float2half_rn(t[tx][ty + j * 8]);
}

// ---------------------------------------------------------------------------
// V transpose (unchanged).
// ---------------------------------------------------------------------------
__global__ void vtrans_kernel(const __nv_bfloat16* __restrict__ qH,
                              const __nv_bfloat16* __restrict__ qL,
                              __nv_bfloat16* __restrict__ vH, __nv_bfloat16* __restrict__ vL)
{
    __shared__ __nv_bfloat16 tH[32][33], tL[32][33];
    const int zc = blockIdx.z, zbb = zc / HH, zhh = zc % HH;
    const __nv_bfloat16* bH = qH + (long long)(zbb * SS) * D3 + 2 * DD + zhh * DHH;
    const __nv_bfloat16* bL = qL + (long long)(zbb * SS) * D3 + 2 * DD + zhh * DHH;
    const int t0 = blockIdx.x * 32, d0 = blockIdx.y * 32;
    const int tx = threadIdx.x & 31, ty = threadIdx.x >> 5;
#pragma unroll
    for (int j = 0; j < 4; j++) {
        long long src = (long long)(t0 + ty + j * 8) * D3 + d0 + tx;
        tH[ty + j * 8][tx] = bH[src];
        tL[ty + j * 8][tx] = bL[src];
    }
    __syncthreads();
    __nv_bfloat16* oH = vH + (long long)zc * DHH * SS;
    __nv_bfloat16* oL = vL + (long long)zc * DHH * SS;
#pragma unroll
    for (int j = 0; j < 4; j++) {
        long long dst = (long long)(d0 + ty + j * 8) * SS + t0 + tx;
        oH[dst] = tH[tx][ty + j * 8];
        oL[dst] = tL[tx][ty + j * 8];
    }
}

// ---------------------------------------------------------------------------
// out = LN(a + b [+ gates@b2]) * g + beta ; optional half output; optional
// fused MoE gate: gatesOut = softmax(out @ gw^T + gb).
// ---------------------------------------------------------------------------
__global__ void ln_kernel(const float* __restrict__ a, const float* __restrict__ b,
                          const float* __restrict__ g, const float* __restrict__ beta,
                          float* __restrict__ outF, __half* __restrict__ oT,
                          const float* __restrict__ gates, const float* __restrict__ b2,
                          const float* __restrict__ gw, const float* __restrict__ gb,
                          float* __restrict__ gatesOut)
{
    long long row = blockIdx.x;
    const float* ar = a + row * DD;
    const float* br = b + row * DD;
    __shared__ float red[256];
    __shared__ float gpart[8][EE];
    __shared__ float gsum[EE];
    int tid = threadIdx.x;
    int wrp = tid >> 5, lane = tid & 31;

    float gt[EE];
    if (gates) {
#pragma unroll
        for (int e = 0; e < EE; e++) gt[e] = gates[row * EE + e];
    }

    float v[4]; float s = 0.f;
#pragma unroll
    for (int i = 0; i < 4; i++) {
        int c = tid + i * 256;
        float x = ar[c] + br[c];
        if (gates) {
            float s2 = 0.f;
#pragma unroll
            for (int e = 0; e < EE; e++) s2 += gt[e] * b2[e * DD + c];
            x += s2;
        }
        v[i] = x; s += x;
    }
    red[tid] = s; __syncthreads();
    for (int t = 128; t; t >>= 1) { if (tid < t) red[tid] += red[tid + t]; __syncthreads(); }
    float mean = red[0] * (1.f / DD); __syncthreads();

    float sq = 0.f;
#pragma unroll
    for (int i = 0; i < 4; i++) { float d = v[i] - mean; sq += d * d; }
    red[tid] = sq; __syncthreads();
    for (int t = 128; t; t >>= 1) { if (tid < t) red[tid] += red[tid + t]; __syncthreads(); }
    float inv = rsqrtf(red[0] * (1.f / DD) + 1e-5f);

    float o4[4];
#pragma unroll
    for (int i = 0; i < 4; i++) {
        int c = tid + i * 256;
        float o = (v[i] - mean) * inv * g[c] + beta[c];
        o4[i] = o;
        outF[row * DD + c] = o;
        if (oT) oT[row * DD + c] = __float2half_rn(o);
    }

    if (gw) {
        float p[EE];
#pragma unroll
        for (int e = 0; e < EE; e++) p[e] = 0.f;
#pragma unroll
        for (int i = 0; i < 4; i++) {
            int c = tid + i * 256;
            float ov = o4[i];
#pragma unroll
            for (int e = 0; e < EE; e++) p[e] += ov * gw[e * DD + c];
        }
#pragma unroll
        for (int e = 0; e < EE; e++)
            for (int off = 16; off; off >>= 1)
                p[e] += __shfl_xor_sync(0xffffffff, p[e], off);
        if (lane == 0) {
#pragma unroll
            for (int e = 0; e < EE; e++) gpart[wrp][e] = p[e];
        }
        __syncthreads();
        if (tid < EE) {
            float sg = 0.f;
#pragma unroll
            for (int wq = 0; wq < 8; wq++) sg += gpart[wq][tid];
            gsum[tid] = sg + gb[tid];
        }
        __syncthreads();
        if (tid == 0) {
            float mx = -3.4e38f;
#pragma unroll
            for (int e = 0; e < EE; e++) mx = fmaxf(mx, gsum[e]);
            float sm = 0.f;
            float pe[EE];
#pragma unroll
            for (int e = 0; e < EE; e++) { pe[e] = expf(gsum[e] - mx); sm += pe[e]; }
            float invs = 1.f / sm;
#pragma unroll
            for (int e = 0; e < EE; e++) gatesOut[row * EE + e] = pe[e] * invs;
        }
    }
}

// ---------------------------------------------------------------------------
// Host orchestration (graph-capturable: launches only).
// ---------------------------------------------------------------------------
extern "C" void kernel_launch(void* const* d_in, const int* in_sizes, int n_in,
                              void* d_out, int out_size)
{
    const float* src        = (const float*)d_in[0];
    const float* in_proj_w  = (const float*)d_in[2];
    const float* in_proj_b  = (const float*)d_in[3];
    const float* out_proj_w = (const float*)d_in[4];
    const float* out_proj_b = (const float*)d_in[5];
    const float* gate_w     = (const float*)d_in[6];
    const float* gate_b     = (const float*)d_in[7];
    const float* w1         = (const float*)d_in[8];
    const float* b1         = (const float*)d_in[9];
    const float* w2         = (const float*)d_in[10];
    const float* b2         = (const float*)d_in[11];
    const float* ln1_g      = (const float*)d_in[12];
    const float* ln1_b      = (const float*)d_in[13];
    const float* ln2_g      = (const float*)d_in[14];
    const float* ln2_b      = (const float*)d_in[15];
    float* out = (float*)d_out;

    float *attn, *x, *ff, *gates;
    cudaGetSymbolAddress((void**)&attn,   g_attn);
    cudaGetSymbolAddress((void**)&x,      g_x);
    cudaGetSymbolAddress((void**)&ff,     g_ff);
    cudaGetSymbolAddress((void**)&gates,  g_gates);

    __nv_bfloat16 *srcH,*srcL,*wqH,*wqL,*woH,*woL;
    __nv_bfloat16 *qkvH,*qkvL,*vtH,*vtL,*ctxH,*ctxL;
    __half *xT,*w1T,*w2T,*hT;
    cudaGetSymbolAddress((void**)&srcH, g_srcH); cudaGetSymbolAddress((void**)&srcL, g_srcL);
    cudaGetSymbolAddress((void**)&wqH,  g_wqH);  cudaGetSymbolAddress((void**)&wqL,  g_wqL);
    cudaGetSymbolAddress((void**)&woH,  g_woH);  cudaGetSymbolAddress((void**)&woL,  g_woL);
    cudaGetSymbolAddress((void**)&qkvH, g_qkvH); cudaGetSymbolAddress((void**)&qkvL, g_qkvL);
    cudaGetSymbolAddress((void**)&vtH,  g_vtH);  cudaGetSymbolAddress((void**)&vtL,  g_vtL);
    cudaGetSymbolAddress((void**)&ctxH, g_ctxH); cudaGetSymbolAddress((void**)&ctxL, g_ctxL);
    cudaGetSymbolAddress((void**)&xT,   g_xT);   cudaGetSymbolAddress((void**)&w1T,  g_w1T);
    cudaGetSymbolAddress((void**)&w2T,  g_w2T);  cudaGetSymbolAddress((void**)&hT,   g_hT);

    const int SM128 = 2 * (2 * 10240 + 2 * 128 * 80);           // 81920
    const int SMH   = 2 * 36864;                                // 73728
    const int SMFA  = 2 * 18432 + 2 * (2 * 18432 + 2 * 17408);  // 180224
    cudaFuncSetAttribute(mma_gemm<128,true >, cudaFuncAttributeMaxDynamicSharedMemorySize, SM128);
    cudaFuncSetAttribute(mma_gemm<128,false>, cudaFuncAttributeMaxDynamicSharedMemorySize, SM128);
    cudaFuncSetAttribute(mma_gemm_f16<true ,true ,true >, cudaFuncAttributeMaxDynamicSharedMemorySize, SMH);
    cudaFuncSetAttribute(mma_gemm_f16<false,false,false>, cudaFuncAttributeMaxDynamicSharedMemorySize, SMH);
    cudaFuncSetAttribute(flash_kernel, cudaFuncAttributeMaxDynamicSharedMemorySize, SMFA);

    dim3 blk(256);

    // ---- conversions ----
    split_kernel<<<2048, 256>>>(src,        srcH, srcL, (long long)NTOK * DD);
    split_kernel<<<2048, 256>>>(in_proj_w,  wqH,  wqL,  (long long)D3 * DD);
    split_kernel<<<1024, 256>>>(out_proj_w, woH,  woL,  (long long)DD * DD);
    // w1 [E][D][FF] -> w1T half [E*FF][D]
    thalf_kernel<<<dim3(FFF/32, DD/32, EE), blk>>>(w1, w1T, FFF, DD,
        (long long)DD * FFF, (long long)FFF * DD);
    // w2 [E][FF][D] -> w2T half [D][E*FF]
    thalf_kernel<<<dim3(DD/32, FFF/32, EE), blk>>>(w2, w2T, DD, EFF,
        (long long)FFF * DD, (long long)FFF);

    // ---- 1. qkv pair = src @ in_proj_w^T + b ----
    mma_gemm<128,true><<<dim3(D3/128, NTOK/128, 1), blk, SM128>>>(
        srcH, srcL, wqH, wqL, nullptr, qkvH, qkvL,
        DD, DD, DD, D3, 1, 0,0, 0,0, 0,0, in_proj_b, 1.f);

    // ---- 2. v transpose ----
    vtrans_kernel<<<dim3(SS/32, DHH/32, BB*HH), blk>>>(qkvH, qkvL, vtH, vtL);

    // ---- 3. flash attention -> ctx pair ----
    flash_kernel<<<dim3(SS/128, 1, BB*HH), blk, SMFA>>>(
        qkvH, qkvL, vtH, vtL, ctxH, ctxL);

    // ---- 4. attn = ctx @ out_proj_w^T + b (fp32) ----
    mma_gemm<128,false><<<dim3(DD/128, NTOK/128, 1), blk, SM128>>>(
        ctxH, ctxL, woH, woL, attn, nullptr, nullptr,
        DD, DD, DD, DD, 1, 0,0, 0,0, 0,0, out_proj_b, 1.f);

    // ---- 5. x = LN1(src + attn), fp32 + fp16 + fused gate ----
    ln_kernel<<<NTOK, blk>>>(src, attn, ln1_g, ln1_b, x, xT, nullptr, nullptr,
                             gate_w, gate_b, gates);

    // ---- 6. h' half = gate * relu(x @ w1T^T + b1)   [4096, 16384], fp16 ----
    mma_gemm_f16<true,true,true><<<dim3(EFF/128, NTOK/128, 1), blk, SMH>>>(
        xT, w1T, nullptr, hT, DD, DD, DD, EFF, b1, gates);

    // ---- 7. ff = h' @ w2T^T (fp32), K=16384, fp16 ----
    mma_gemm_f16<false,false,false><<<dim3(DD/128, NTOK/128, 1), blk, SMH>>>(
        hT, w2T, ff, nullptr, EFF, EFF, EFF, DD, nullptr, nullptr);

    // ---- 8. out = LN2(x + ff + gates@b2) ----
    ln_kernel<<<NTOK, blk>>>(x, ff, ln2_g, ln2_b, out, nullptr, gates, b2,
                             nullptr, nullptr, nullptr);
}

// round 10
// speedup vs baseline: 2.8016x; 1.2730x over previous
#include <cuda_runtime.h>
#include <cuda_fp16.h>

#define BB 4
#define SS 1024
#define DD 1024
#define HH 16
#define DHH 64
#define EE 8
#define FFF 2048
#define NTOK (BB*SS)
#define D3 (3*DD)
#define EFF (EE*FFF)

// ---------------------------------------------------------------------------
// Scratch (static device globals — allocations are forbidden).
// ---------------------------------------------------------------------------
__device__ float g_attn[(size_t)NTOK*DD];
__device__ float g_x[(size_t)NTOK*DD];
__device__ float g_ff[(size_t)NTOK*DD];
__device__ float g_gates[(size_t)NTOK*EE];

__device__ __half g_srcT[(size_t)NTOK*DD];
__device__ __half g_wqT[(size_t)D3*DD];
__device__ __half g_woT[(size_t)DD*DD];
__device__ __half g_qkvT[(size_t)NTOK*D3];
__device__ __half g_vtT[(size_t)BB*HH*DHH*SS];
__device__ __half g_ctxT[(size_t)NTOK*DD];
__device__ __half g_xT[(size_t)NTOK*DD];
__device__ __half g_w1T[(size_t)EFF*DD];
__device__ __half g_w2T[(size_t)DD*EFF];
__device__ __half g_hT[(size_t)NTOK*EFF];

// ---------------------------------------------------------------------------
// PTX helpers (sm_80-era instructions only — legal on plain sm_103 target).
// ---------------------------------------------------------------------------
__device__ __forceinline__ unsigned smem_u32(const void* p){
    unsigned a;
    asm("{ .reg .u64 t; cvta.to.shared.u64 t, %1; cvt.u32.u64 %0, t; }" : "=r"(a) : "l"(p));
    return a;
}
__device__ __forceinline__ void cp16(unsigned saddr, const void* gaddr){
    asm volatile("cp.async.cg.shared.global [%0], [%1], 16;" :: "r"(saddr), "l"(gaddr));
}
#define CP_COMMIT() asm volatile("cp.async.commit_group;" ::: "memory")
template<int N> __device__ __forceinline__ void cp_wait(){
    asm volatile("cp.async.wait_group %0;" :: "n"(N) : "memory");
}
__device__ __forceinline__ void ldsm_x4(unsigned addr, unsigned* r){
    asm volatile("ldmatrix.sync.aligned.m8n8.x4.shared.b16 {%0,%1,%2,%3}, [%4];"
        : "=r"(r[0]),"=r"(r[1]),"=r"(r[2]),"=r"(r[3]) : "r"(addr));
}
__device__ __forceinline__ void mma16816h(float* c, const unsigned* a, const unsigned* b){
    asm volatile("mma.sync.aligned.m16n8k16.row.col.f32.f16.f16.f32 "
        "{%0,%1,%2,%3}, {%4,%5,%6,%7}, {%8,%9}, {%0,%1,%2,%3};"
        : "+f"(c[0]),"+f"(c[1]),"+f"(c[2]),"+f"(c[3])
        : "r"(a[0]),"r"(a[1]),"r"(a[2]),"r"(a[3]), "r"(b[0]),"r"(b[1]));
}
__device__ __forceinline__ unsigned packh2(float lo, float hi){
    __half2 t = __floats2half2_rn(lo, hi);
    return *reinterpret_cast<unsigned*>(&t);
}

// ---------------------------------------------------------------------------
// fp16 single-pass GEMM.  C = epi( A @ B^T ), A [M,K] half (lda), B [N,K]
// half (ldb). BM=128, BN=128, BK=64, warp tile 64x32, 2 CTAs/SM.
// Epilogue staged through smem for coalesced 16B stores.
// ---------------------------------------------------------------------------
template<bool RELU, bool GATE, bool OUTHALF>
__global__ void __launch_bounds__(256, 2) mma_gemm_f16(
    const __half* __restrict__ A, const __half* __restrict__ Bm,
    float* __restrict__ C, __half* __restrict__ Ch,
    int K, int lda, int ldb, int ldc,
    const float* __restrict__ bias, const float* __restrict__ gates)
{
    constexpr int BN = 128;
    constexpr int MF = 4;
    constexpr int NF = 4;
    constexpr unsigned APITCH = 144u;
    constexpr unsigned ABYTES = 128u * APITCH;
    constexpr unsigned BNB    = 128u * APITCH;
    constexpr unsigned STAGE  = ABYTES + BNB;

    extern __shared__ char smem[];
    const unsigned sb = smem_u32(smem);
    const int tid = threadIdx.x, w = tid >> 5, lane = tid & 31;
    const int wy = w >> 2, wx = w & 3;
    const int wm0 = wy * 64, wn0 = wx * 32;

    const int row0 = blockIdx.y * 128;
    const int col0 = blockIdx.x * BN;
    const int NC = K >> 6;

    auto loadChunk = [&](int c, int s){
        const unsigned st = sb + (unsigned)s * STAGE;
        for (int i = tid; i < 1024; i += 256) {
            int r = i >> 3, ch = i & 7;
            unsigned so = st + (unsigned)r * APITCH + (unsigned)ch * 16u;
            cp16(so, (const char*)(A + (long long)(row0 + r) * lda + c * 64) + ch * 16);
        }
        for (int i = tid; i < 1024; i += 256) {
            int r = i >> 3, ch = i & 7;
            unsigned so = st + ABYTES + (unsigned)r * APITCH + (unsigned)ch * 16u;
            cp16(so, (const char*)(Bm + (long long)(col0 + r) * ldb + c * 64) + ch * 16);
        }
        CP_COMMIT();
    };

    float cr[MF][NF][4];
#pragma unroll
    for (int i = 0; i < MF; i++)
#pragma unroll
        for (int j = 0; j < NF; j++)
#pragma unroll
            for (int q = 0; q < 4; q++) cr[i][j][q] = 0.f;

    loadChunk(0, 0);

    for (int c = 0; c < NC; c++) {
        if (c + 1 < NC) { loadChunk(c + 1, (c + 1) & 1); cp_wait<1>(); }
        else            { cp_wait<0>(); }
        __syncthreads();

        const unsigned st = sb + (unsigned)(c & 1) * STAGE;
        const unsigned aB = st, bB = st + ABYTES;

#pragma unroll
        for (int ks = 0; ks < 4; ks++) {
            const unsigned aRow = (unsigned)(wm0 + (lane & 15)) * APITCH
                                + (unsigned)(ks * 32) + (unsigned)((lane >> 4) * 16);
            const unsigned bRow = (unsigned)(wn0 + (lane & 7) + ((lane >> 4) << 3)) * APITCH
                                + (unsigned)(ks * 32) + (unsigned)(((lane >> 3) & 1) * 16);

            unsigned aF[MF][4];
#pragma unroll
            for (int mf = 0; mf < MF; mf++)
                ldsm_x4(aB + aRow + (unsigned)(mf * 16) * APITCH, aF[mf]);

            unsigned bF[NF][2];
#pragma unroll
            for (int nfp = 0; nfp < 2; nfp++) {
                unsigned t[4];
                ldsm_x4(bB + bRow + (unsigned)(nfp * 16) * APITCH, t);
                bF[nfp*2][0] = t[0]; bF[nfp*2][1] = t[1];
                bF[nfp*2+1][0] = t[2]; bF[nfp*2+1][1] = t[3];
            }

#pragma unroll
            for (int mf = 0; mf < MF; mf++)
#pragma unroll
                for (int nf = 0; nf < NF; nf++)
                    mma16816h(cr[mf][nf], aF[mf], bF[nf]);
        }
        __syncthreads();
    }

    constexpr unsigned PH = (unsigned)BN * 2u + 16u;
    constexpr unsigned PF = (unsigned)BN * 4u + 16u;

#pragma unroll
    for (int mf = 0; mf < MF; mf++) {
        const int ml = wm0 + mf * 16 + (lane >> 2);
#pragma unroll
        for (int nf = 0; nf < NF; nf++) {
            const int nl = wn0 + nf * 8 + (lane & 3) * 2;
            const int n  = col0 + nl;
            float a0 = cr[mf][nf][0], a1 = cr[mf][nf][1];
            float b0 = cr[mf][nf][2], b1 = cr[mf][nf][3];
            if (bias) { float bb0 = bias[n], bb1 = bias[n+1]; a0 += bb0; a1 += bb1; b0 += bb0; b1 += bb1; }
            if (RELU) { a0 = fmaxf(a0,0.f); a1 = fmaxf(a1,0.f); b0 = fmaxf(b0,0.f); b1 = fmaxf(b1,0.f); }
            if (GATE) {
                float g0 = gates[(long long)(row0+ml) * EE + (n / FFF)];
                float g1 = gates[(long long)(row0+ml+8) * EE + (n / FFF)];
                a0 *= g0; a1 *= g0; b0 *= g1; b1 *= g1;
            }
            if (OUTHALF) {
                *reinterpret_cast<__half2*>(smem + (unsigned)ml * PH + (unsigned)nl * 2u)
                    = __floats2half2_rn(a0, a1);
                *reinterpret_cast<__half2*>(smem + (unsigned)(ml+8) * PH + (unsigned)nl * 2u)
                    = __floats2half2_rn(b0, b1);
            } else {
                *reinterpret_cast<float2*>(smem + (unsigned)ml * PF + (unsigned)nl * 4u) = make_float2(a0, a1);
                *reinterpret_cast<float2*>(smem + (unsigned)(ml+8) * PF + (unsigned)nl * 4u) = make_float2(b0, b1);
            }
        }
    }
    __syncthreads();

    if (OUTHALF) {
        constexpr int CH = BN / 8;
        for (int i = tid; i < 128 * CH; i += 256) {
            int r = i / CH, ch = i % CH;
            uint4 v = *reinterpret_cast<uint4*>(smem + (unsigned)r * PH + (unsigned)ch * 16u);
            *reinterpret_cast<uint4*>(Ch + (long long)(row0 + r) * ldc + col0 + ch * 8) = v;
        }
    } else {
        constexpr int CHF = BN / 4;
        for (int i = tid; i < 128 * CHF; i += 256) {
            int r = i / CHF, ch = i % CHF;
            uint4 v = *reinterpret_cast<uint4*>(smem + (unsigned)r * PF + (unsigned)ch * 16u);
            *reinterpret_cast<uint4*>(C + (long long)(row0 + r) * ldc + col0 + ch * 4) = v;
        }
    }
}

// ---------------------------------------------------------------------------
// fp16 flash attention: one CTA = (b,h) x 128-query tile, 8 warps x 16 rows.
// S = Q@K^T fp16, online softmax fp32, O += P@V fp16 (P packed in regs).
// ---------------------------------------------------------------------------
__global__ void __launch_bounds__(256) flash_kernel(
    const __half* __restrict__ qkvT, const __half* __restrict__ vtT,
    __half* __restrict__ cT)
{
    constexpr unsigned QP = 144u, VP = 272u;
    constexpr unsigned QBYTES = 128u * QP;      // 18432
    constexpr unsigned KBYTES = 128u * QP;      // 18432
    constexpr unsigned VBYTES = 64u * VP;       // 17408
    constexpr unsigned STAGE  = KBYTES + VBYTES;

    extern __shared__ char smem[];
    const unsigned sb = smem_u32(smem);
    const int tid = threadIdx.x, w = tid >> 5, lane = tid & 31;

    const int bh = blockIdx.z, b = bh >> 4, h = bh & 15;
    const int q0 = blockIdx.x * 128;

    const __half* Q = qkvT + ((long long)b * SS) * D3 + h * DHH;
    const __half* Kp = Q + DD;
    const __half* V = vtT + (long long)bh * DHH * SS;

    const unsigned qB = sb;
    const unsigned kvBase = sb + QBYTES;

    for (int i = tid; i < 1024; i += 256) {
        int r = i >> 3, ch = i & 7;
        cp16(qB + (unsigned)r * QP + (unsigned)ch * 16u,
             (const char*)(Q + (long long)(q0 + r) * D3) + ch * 16);
    }

    auto loadKV = [&](int t, int s){
        const unsigned st = kvBase + (unsigned)s * STAGE;
        const int k0 = t * 128;
        for (int i = tid; i < 1024; i += 256) {
            int r = i >> 3, ch = i & 7;
            cp16(st + (unsigned)r * QP + (unsigned)ch * 16u,
                 (const char*)(Kp + (long long)(k0 + r) * D3) + ch * 16);
        }
        const unsigned vst = st + KBYTES;
        for (int i = tid; i < 1024; i += 256) {
            int r = i >> 4, ch = i & 15;
            cp16(vst + (unsigned)r * VP + (unsigned)ch * 16u,
                 (const char*)(V + (long long)r * SS + k0) + ch * 16);
        }
        CP_COMMIT();
    };
    loadKV(0, 0);

    float o[8][4];
#pragma unroll
    for (int i = 0; i < 8; i++)
#pragma unroll
        for (int q = 0; q < 4; q++) o[i][q] = 0.f;
    float m0 = -1e30f, m1 = -1e30f, l0 = 0.f, l1 = 0.f;
    const float scale = 0.125f;

    for (int t = 0; t < 8; t++) {
        if (t + 1 < 8) { loadKV(t + 1, (t + 1) & 1); cp_wait<1>(); }
        else           { cp_wait<0>(); }
        __syncthreads();

        const unsigned st = kvBase + (unsigned)(t & 1) * STAGE;
        const unsigned kB = st, vB = st + KBYTES;

        float sc[16][4];
#pragma unroll
        for (int i = 0; i < 16; i++)
#pragma unroll
            for (int q = 0; q < 4; q++) sc[i][q] = 0.f;

#pragma unroll
        for (int ks = 0; ks < 4; ks++) {
            const unsigned aRow = (unsigned)(w * 16 + (lane & 15)) * QP
                                + (unsigned)(ks * 32) + (unsigned)((lane >> 4) * 16);
            unsigned aF[4];
            ldsm_x4(qB + aRow, aF);
#pragma unroll
            for (int nfp = 0; nfp < 8; nfp++) {
                const unsigned bo = (unsigned)(nfp * 16 + (lane & 7) + ((lane >> 4) << 3)) * QP
                                  + (unsigned)(ks * 32) + (unsigned)(((lane >> 3) & 1) * 16);
                unsigned tF[4];
                ldsm_x4(kB + bo, tF);
                mma16816h(sc[nfp*2],   aF, tF);
                mma16816h(sc[nfp*2+1], aF, tF + 2);
            }
        }

        float r0 = -1e30f, r1 = -1e30f;
#pragma unroll
        for (int i = 0; i < 16; i++) {
            r0 = fmaxf(r0, fmaxf(sc[i][0], sc[i][1]));
            r1 = fmaxf(r1, fmaxf(sc[i][2], sc[i][3]));
        }
        r0 = fmaxf(r0, __shfl_xor_sync(0xffffffff, r0, 1));
        r0 = fmaxf(r0, __shfl_xor_sync(0xffffffff, r0, 2));
        r1 = fmaxf(r1, __shfl_xor_sync(0xffffffff, r1, 1));
        r1 = fmaxf(r1, __shfl_xor_sync(0xffffffff, r1, 2));
        const float mn0 = fmaxf(m0, r0 * scale);
        const float mn1 = fmaxf(m1, r1 * scale);
        const float cor0 = __expf(m0 - mn0);
        const float cor1 = __expf(m1 - mn1);
        m0 = mn0; m1 = mn1;

        float s0 = 0.f, s1 = 0.f;
#pragma unroll
        for (int i = 0; i < 16; i++) {
            sc[i][0] = __expf(sc[i][0] * scale - m0);
            sc[i][1] = __expf(sc[i][1] * scale - m0);
            sc[i][2] = __expf(sc[i][2] * scale - m1);
            sc[i][3] = __expf(sc[i][3] * scale - m1);
            s0 += sc[i][0] + sc[i][1];
            s1 += sc[i][2] + sc[i][3];
        }
        s0 += __shfl_xor_sync(0xffffffff, s0, 1);
        s0 += __shfl_xor_sync(0xffffffff, s0, 2);
        s1 += __shfl_xor_sync(0xffffffff, s1, 1);
        s1 += __shfl_xor_sync(0xffffffff, s1, 2);
        l0 = l0 * cor0 + s0;
        l1 = l1 * cor1 + s1;
#pragma unroll
        for (int i = 0; i < 8; i++) {
            o[i][0] *= cor0; o[i][1] *= cor0;
            o[i][2] *= cor1; o[i][3] *= cor1;
        }

#pragma unroll
        for (int kv = 0; kv < 8; kv++) {
            float* p0 = sc[kv*2];
            float* p1 = sc[kv*2+1];
            unsigned aF[4];
            aF[0] = packh2(p0[0], p0[1]);
            aF[1] = packh2(p0[2], p0[3]);
            aF[2] = packh2(p1[0], p1[1]);
            aF[3] = packh2(p1[2], p1[3]);
#pragma unroll
            for (int vf = 0; vf < 4; vf++) {
                const unsigned bo = (unsigned)(vf * 16 + (lane & 7) + ((lane >> 4) << 3)) * VP
                                  + (unsigned)(kv * 2 + ((lane >> 3) & 1)) * 16u;
                unsigned tF[4];
                ldsm_x4(vB + bo, tF);
                mma16816h(o[vf*2],   aF, tF);
                mma16816h(o[vf*2+1], aF, tF + 2);
            }
        }
        __syncthreads();
    }

    const float inv0 = 1.f / l0, inv1 = 1.f / l1;
    const int r = q0 + w * 16 + (lane >> 2);
    const long long tok0 = (long long)(b * SS + r);
    const long long tok1 = tok0 + 8;
#pragma unroll
    for (int nf = 0; nf < 8; nf++) {
        const int d = h * DHH + nf * 8 + (lane & 3) * 2;
        *reinterpret_cast<__half2*>(cT + tok0 * DD + d)
            = __floats2half2_rn(o[nf][0] * inv0, o[nf][1] * inv0);
        *reinterpret_cast<__half2*>(cT + tok1 * DD + d)
            = __floats2half2_rn(o[nf][2] * inv1, o[nf][3] * inv1);
    }
}

// ---------------------------------------------------------------------------
// fp32 -> fp16 (elementwise)
// ---------------------------------------------------------------------------
__global__ void half_kernel(const float* __restrict__ in, __half* __restrict__ ot, long long n)
{
    long long i = (long long)blockIdx.x * blockDim.x + threadIdx.x;
    long long stride = (long long)gridDim.x * blockDim.x;
    for (; i < n; i += stride) ot[i] = __float2half_rn(in[i]);
}

// ---------------------------------------------------------------------------
// Transpose + fp16: in fp32 [R][C] (ldin) -> half [C][R] (ldout), per z.
// ---------------------------------------------------------------------------
__global__ void thalf_kernel(const float* __restrict__ in, __half* __restrict__ ot,
                             int ldin, int ldout, long long inStride, long long outStride)
{
    __shared__ float t[32][33];
    in += (long long)blockIdx.z * inStride;
    ot += (long long)blockIdx.z * outStride;
    const int c0 = blockIdx.x * 32, r0 = blockIdx.y * 32;
    const int tx = threadIdx.x & 31, ty = threadIdx.x >> 5;
#pragma unroll
    for (int j = 0; j < 4; j++)
        t[ty + j * 8][tx] = in[(long long)(r0 + ty + j * 8) * ldin + c0 + tx];
    __syncthreads();
#pragma unroll
    for (int j = 0; j < 4; j++)
        ot[(long long)(c0 + ty + j * 8) * ldout + r0 + tx] = __float2half_rn(t[tx][ty + j * 8]);
}

// ---------------------------------------------------------------------------
// V transpose: qkvT half -> vtT half [bh][DHH][SS].
// ---------------------------------------------------------------------------
__global__ void vtrans_kernel(const __half* __restrict__ qT, __half* __restrict__ vT)
{
    __shared__ __half t[32][33];
    const int zc = blockIdx.z, zbb = zc / HH, zhh = zc % HH;
    const __half* bP = qT + (long long)(zbb * SS) * D3 + 2 * DD + zhh * DHH;
    const int t0 = blockIdx.x * 32, d0 = blockIdx.y * 32;
    const int tx = threadIdx.x & 31, ty = threadIdx.x >> 5;
#pragma unroll
    for (int j = 0; j < 4; j++)
        t[ty + j * 8][tx] = bP[(long long)(t0 + ty + j * 8) * D3 + d0 + tx];
    __syncthreads();
    __half* oP = vT + (long long)zc * DHH * SS;
#pragma unroll
    for (int j = 0; j < 4; j++)
        oP[(long long)(d0 + ty + j * 8) * SS + t0 + tx] = t[tx][ty + j * 8];
}

// ---------------------------------------------------------------------------
// out = LN(a + b [+ gates@b2]) * g + beta ; optional half out; optional
// fused MoE gate: gatesOut = softmax(out @ gw^T + gb).
// ---------------------------------------------------------------------------
__global__ void ln_kernel(const float* __restrict__ a, const float* __restrict__ b,
                          const float* __restrict__ g, const float* __restrict__ beta,
                          float* __restrict__ outF, __half* __restrict__ oT,
                          const float* __restrict__ gates, const float* __restrict__ b2,
                          const float* __restrict__ gw, const float* __restrict__ gb,
                          float* __restrict__ gatesOut)
{
    long long row = blockIdx.x;
    const float* ar = a + row * DD;
    const float* br = b + row * DD;
    __shared__ float red[256];
    __shared__ float gpart[8][EE];
    __shared__ float gsum[EE];
    int tid = threadIdx.x;
    int wrp = tid >> 5, lane = tid & 31;

    float gt[EE];
    if (gates) {
#pragma unroll
        for (int e = 0; e < EE; e++) gt[e] = gates[row * EE + e];
    }

    float v[4]; float s = 0.f;
#pragma unroll
    for (int i = 0; i < 4; i++) {
        int c = tid + i * 256;
        float x = ar[c] + br[c];
        if (gates) {
            float s2 = 0.f;
#pragma unroll
            for (int e = 0; e < EE; e++) s2 += gt[e] * b2[e * DD + c];
            x += s2;
        }
        v[i] = x; s += x;
    }
    red[tid] = s; __syncthreads();
    for (int t = 128; t; t >>= 1) { if (tid < t) red[tid] += red[tid + t]; __syncthreads(); }
    float mean = red[0] * (1.f / DD); __syncthreads();

    float sq = 0.f;
#pragma unroll
    for (int i = 0; i < 4; i++) { float d = v[i] - mean; sq += d * d; }
    red[tid] = sq; __syncthreads();
    for (int t = 128; t; t >>= 1) { if (tid < t) red[tid] += red[tid + t]; __syncthreads(); }
    float inv = rsqrtf(red[0] * (1.f / DD) + 1e-5f);

    float o4[4];
#pragma unroll
    for (int i = 0; i < 4; i++) {
        int c = tid + i * 256;
        float o = (v[i] - mean) * inv * g[c] + beta[c];
        o4[i] = o;
        outF[row * DD + c] = o;
        if (oT) oT[row * DD + c] = __float2half_rn(o);
    }

    if (gw) {
        float p[EE];
#pragma unroll
        for (int e = 0; e < EE; e++) p[e] = 0.f;
#pragma unroll
        for (int i = 0; i < 4; i++) {
            int c = tid + i * 256;
            float ov = o4[i];
#pragma unroll
            for (int e = 0; e < EE; e++) p[e] += ov * gw[e * DD + c];
        }
#pragma unroll
        for (int e = 0; e < EE; e++)
            for (int off = 16; off; off >>= 1)
                p[e] += __shfl_xor_sync(0xffffffff, p[e], off);
        if (lane == 0) {
#pragma unroll
            for (int e = 0; e < EE; e++) gpart[wrp][e] = p[e];
        }
        __syncthreads();
        if (tid < EE) {
            float sg = 0.f;
#pragma unroll
            for (int wq = 0; wq < 8; wq++) sg += gpart[wq][tid];
            gsum[tid] = sg + gb[tid];
        }
        __syncthreads();
        if (tid == 0) {
            float mx = -3.4e38f;
#pragma unroll
            for (int e = 0; e < EE; e++) mx = fmaxf(mx, gsum[e]);
            float sm = 0.f;
            float pe[EE];
#pragma unroll
            for (int e = 0; e < EE; e++) { pe[e] = expf(gsum[e] - mx); sm += pe[e]; }
            float invs = 1.f / sm;
#pragma unroll
            for (int e = 0; e < EE; e++) gatesOut[row * EE + e] = pe[e] * invs;
        }
    }
}

// ---------------------------------------------------------------------------
// Host orchestration (graph-capturable: launches only).
// ---------------------------------------------------------------------------
extern "C" void kernel_launch(void* const* d_in, const int* in_sizes, int n_in,
                              void* d_out, int out_size)
{
    const float* src        = (const float*)d_in[0];
    const float* in_proj_w  = (const float*)d_in[2];
    const float* in_proj_b  = (const float*)d_in[3];
    const float* out_proj_w = (const float*)d_in[4];
    const float* out_proj_b = (const float*)d_in[5];
    const float* gate_w     = (const float*)d_in[6];
    const float* gate_b     = (const float*)d_in[7];
    const float* w1         = (const float*)d_in[8];
    const float* b1         = (const float*)d_in[9];
    const float* w2         = (const float*)d_in[10];
    const float* b2         = (const float*)d_in[11];
    const float* ln1_g      = (const float*)d_in[12];
    const float* ln1_b      = (const float*)d_in[13];
    const float* ln2_g      = (const float*)d_in[14];
    const float* ln2_b      = (const float*)d_in[15];
    float* out = (float*)d_out;

    float *attn, *x, *ff, *gates;
    cudaGetSymbolAddress((void**)&attn,   g_attn);
    cudaGetSymbolAddress((void**)&x,      g_x);
    cudaGetSymbolAddress((void**)&ff,     g_ff);
    cudaGetSymbolAddress((void**)&gates,  g_gates);

    __half *srcT,*wqT,*woT,*qkvT,*vtT,*ctxT,*xT,*w1T,*w2T,*hT;
    cudaGetSymbolAddress((void**)&srcT, g_srcT);
    cudaGetSymbolAddress((void**)&wqT,  g_wqT);
    cudaGetSymbolAddress((void**)&woT,  g_woT);
    cudaGetSymbolAddress((void**)&qkvT, g_qkvT);
    cudaGetSymbolAddress((void**)&vtT,  g_vtT);
    cudaGetSymbolAddress((void**)&ctxT, g_ctxT);
    cudaGetSymbolAddress((void**)&xT,   g_xT);
    cudaGetSymbolAddress((void**)&w1T,  g_w1T);
    cudaGetSymbolAddress((void**)&w2T,  g_w2T);
    cudaGetSymbolAddress((void**)&hT,   g_hT);

    const int SMH  = 2 * 36864;                       // 73728
    const int SMFA = 18432 + 2 * (18432 + 17408);     // 90112
    cudaFuncSetAttribute(mma_gemm_f16<false,false,true >, cudaFuncAttributeMaxDynamicSharedMemorySize, SMH);
    cudaFuncSetAttribute(mma_gemm_f16<false,false,false>, cudaFuncAttributeMaxDynamicSharedMemorySize, SMH);
    cudaFuncSetAttribute(mma_gemm_f16<true ,true ,true >, cudaFuncAttributeMaxDynamicSharedMemorySize, SMH);
    cudaFuncSetAttribute(flash_kernel, cudaFuncAttributeMaxDynamicSharedMemorySize, SMFA);

    dim3 blk(256);

    // ---- conversions ----
    half_kernel<<<2048, 256>>>(src,        srcT, (long long)NTOK * DD);
    half_kernel<<<2048, 256>>>(in_proj_w,  wqT,  (long long)D3 * DD);
    half_kernel<<<1024, 256>>>(out_proj_w, woT,  (long long)DD * DD);
    thalf_kernel<<<dim3(FFF/32, DD/32, EE), blk>>>(w1, w1T, FFF, DD,
        (long long)DD * FFF, (long long)FFF * DD);
    thalf_kernel<<<dim3(DD/32, FFF/32, EE), blk>>>(w2, w2T, DD, EFF,
        (long long)FFF * DD, (long long)FFF);

    // ---- 1. qkv = src @ in_proj_w^T + b (half) ----
    mma_gemm_f16<false,false,true><<<dim3(D3/128, NTOK/128, 1), blk, SMH>>>(
        srcT, wqT, nullptr, qkvT, DD, DD, DD, D3, in_proj_b, nullptr);

    // ---- 2. v transpose ----
    vtrans_kernel<<<dim3(SS/32, DHH/32, BB*HH), blk>>>(qkvT, vtT);

    // ---- 3. flash attention -> ctx half ----
    flash_kernel<<<dim3(SS/128, 1, BB*HH), blk, SMFA>>>(qkvT, vtT, ctxT);

    // ---- 4. attn = ctx @ out_proj_w^T + b (fp32) ----
    mma_gemm_f16<false,false,false><<<dim3(DD/128, NTOK/128, 1), blk, SMH>>>(
        ctxT, woT, attn, nullptr, DD, DD, DD, DD, out_proj_b, nullptr);

    // ---- 5. x = LN1(src + attn), fp32 + fp16 + fused gate ----
    ln_kernel<<<NTOK, blk>>>(src, attn, ln1_g, ln1_b, x, xT, nullptr, nullptr,
                             gate_w, gate_b, gates);

    // ---- 6. h' = gate * relu(x @ w1T^T + b1)  half [4096, 16384] ----
    mma_gemm_f16<true,true,true><<<dim3(EFF/128, NTOK/128, 1), blk, SMH>>>(
        xT, w1T, nullptr, hT, DD, DD, DD, EFF, b1, gates);

    // ---- 7. ff = h' @ w2T^T (fp32), K=16384 ----
    mma_gemm_f16<false,false,false><<<dim3(DD/128, NTOK/128, 1), blk, SMH>>>(
        hT, w2T, ff, nullptr, EFF, EFF, EFF, DD, nullptr, nullptr);

    // ---- 8. out = LN2(x + ff + gates@b2) ----
    ln_kernel<<<NTOK, blk>>>(x, ff, ln2_g, ln2_b, out, nullptr, gates, b2,
                             nullptr, nullptr, nullptr);
}